// round 5
// baseline (speedup 1.0000x reference)
#include <cuda_runtime.h>
#include <cuda_bf16.h>
#include <cstdint>
#include <math.h>

// Problem constants
#define BB 2
#define SS 2048
#define DD 1024
#define NH 16
#define HD 64
#define MM (BB*SS)      // 4096
#define QSCALE 0.18033688011112042f   // 0.125 * log2(e)
#define QMAX 16256.0f                 // 127*128

// ---------------------------------------------------------------------------
// Scratch (device globals)
// ---------------------------------------------------------------------------
__device__ __align__(16) int8_t g_A8h[MM*DD],  g_A8l[MM*DD];      // residual limbs
__device__ __align__(16) int8_t g_A28h[MM*DD], g_A28l[MM*DD];     // attn-out limbs
__device__ __align__(16) int8_t g_WQ8h[DD*DD], g_WQ8l[DD*DD];
__device__ __align__(16) int8_t g_WK8h[DD*DD], g_WK8l[DD*DD];
__device__ __align__(16) int8_t g_WV8h[DD*DD], g_WV8l[DD*DD];
__device__ __align__(16) int8_t g_WO8h[DD*DD], g_WO8l[DD*DD];     // transposed W_O limbs
__device__ float g_sA[MM], g_sA2[MM];
__device__ float g_sWQ[DD], g_sWK[DD], g_sWV[DD], g_sWO[DD];
__device__ __align__(16) __nv_bfloat16 g_Qhi[BB*NH*SS*HD], g_Qlo[BB*NH*SS*HD];
__device__ __align__(16) __nv_bfloat16 g_Khi[BB*NH*SS*HD], g_Klo[BB*NH*SS*HD];
__device__ __align__(16) __nv_bfloat16 g_Vhi[BB*NH*SS*HD], g_Vlo[BB*NH*SS*HD];
__device__ float g_attn[MM*DD];

// ---------------------------------------------------------------------------
// helpers
// ---------------------------------------------------------------------------
__device__ __forceinline__ uint32_t smem_u32(const void* p) {
    uint32_t a;
    asm("{ .reg .u64 t; cvta.to.shared.u64 t, %1; cvt.u32.u64 %0, t; }" : "=r"(a) : "l"(p));
    return a;
}
#define LDSM_X4(r, a) asm volatile("ldmatrix.sync.aligned.m8n8.x4.shared.b16 {%0,%1,%2,%3}, [%4];" \
  : "=r"((r)[0]),"=r"((r)[1]),"=r"((r)[2]),"=r"((r)[3]) : "r"(a))
#define LDSM_X4T(r, a) asm volatile("ldmatrix.sync.aligned.m8n8.x4.trans.shared.b16 {%0,%1,%2,%3}, [%4];" \
  : "=r"((r)[0]),"=r"((r)[1]),"=r"((r)[2]),"=r"((r)[3]) : "r"(a))
#define LDSM_X2(r, a) asm volatile("ldmatrix.sync.aligned.m8n8.x2.shared.b16 {%0,%1}, [%2];" \
  : "=r"((r)[0]),"=r"((r)[1]) : "r"(a))
#define MMA_BF16(d, a, b) asm volatile( \
  "mma.sync.aligned.m16n8k16.row.col.f32.bf16.bf16.f32 {%0,%1,%2,%3},{%4,%5,%6,%7},{%8,%9},{%0,%1,%2,%3};" \
  : "+f"((d)[0]), "+f"((d)[1]), "+f"((d)[2]), "+f"((d)[3]) \
  : "r"((a)[0]),"r"((a)[1]),"r"((a)[2]),"r"((a)[3]), "r"((b)[0]),"r"((b)[1]))
#define MMA_S8(d, a, b) asm volatile( \
  "mma.sync.aligned.m16n8k32.row.col.s32.s8.s8.s32 {%0,%1,%2,%3},{%4,%5,%6,%7},{%8,%9},{%0,%1,%2,%3};" \
  : "+r"((d)[0]), "+r"((d)[1]), "+r"((d)[2]), "+r"((d)[3]) \
  : "r"((a)[0]),"r"((a)[1]),"r"((a)[2]),"r"((a)[3]), "r"((b)[0]),"r"((b)[1]))
#define CP_ASYNC16(dst, src) asm volatile("cp.async.cg.shared.global [%0], [%1], 16;" :: "r"(dst), "l"(src))
#define CP_COMMIT() asm volatile("cp.async.commit_group;" ::: "memory")
#define CP_WAIT0()  asm volatile("cp.async.wait_group 0;" ::: "memory")
#define CP_WAIT1()  asm volatile("cp.async.wait_group 1;" ::: "memory")

__device__ __forceinline__ float ex2f(float x) {
    float y; asm("ex2.approx.ftz.f32 %0, %1;" : "=f"(y) : "f"(x)); return y;
}
__device__ __forceinline__ uint32_t packbf(__nv_bfloat16 a, __nv_bfloat16 b) {
    return (uint32_t)__bfloat16_as_ushort(a) | ((uint32_t)__bfloat16_as_ushort(b) << 16);
}
__device__ __forceinline__ void split_pack(float x0, float x1, uint32_t& hi, uint32_t& lo) {
    __nv_bfloat16 h0 = __float2bfloat16(x0), h1 = __float2bfloat16(x1);
    hi = packbf(h0, h1);
    __nv_bfloat16 g0 = __float2bfloat16(x0 - __bfloat162float(h0));
    __nv_bfloat16 g1 = __float2bfloat16(x1 - __bfloat162float(h1));
    lo = packbf(g0, g1);
}
__device__ __forceinline__ void q2(float t, int8_t& h, int8_t& l) {
    int hi = __float2int_rn(t * 0.0078125f);
    int lo = __float2int_rn(t - (float)hi * 128.0f);
    h = (int8_t)hi; l = (int8_t)lo;
}

// ---------------------------------------------------------------------------
// per-row 2-limb int8 quantization: one warp per row of 1024 floats
// ---------------------------------------------------------------------------
__global__ __launch_bounds__(256) void quant_rows(const float* __restrict__ src,
                                                  int8_t* __restrict__ hi,
                                                  int8_t* __restrict__ lo,
                                                  float* __restrict__ scale)
{
    const int row  = blockIdx.x * 8 + (threadIdx.x >> 5);
    const int lane = threadIdx.x & 31;
    const float4* s = (const float4*)(src + (size_t)row * DD);
    float4 v[8];
    float mx = 0.f;
    #pragma unroll
    for (int g = 0; g < 8; g++) {
        v[g] = s[lane + g * 32];
        mx = fmaxf(mx, fmaxf(fmaxf(fabsf(v[g].x), fabsf(v[g].y)),
                             fmaxf(fabsf(v[g].z), fabsf(v[g].w))));
    }
    #pragma unroll
    for (int o = 16; o; o >>= 1) mx = fmaxf(mx, __shfl_xor_sync(0xffffffffu, mx, o));
    const float inv = (mx > 0.f) ? QMAX / mx : 0.f;
    if (lane == 0) scale[row] = mx / QMAX;
    #pragma unroll
    for (int g = 0; g < 8; g++) {
        int8_t h[4], l[4];
        q2(v[g].x * inv, h[0], l[0]);
        q2(v[g].y * inv, h[1], l[1]);
        q2(v[g].z * inv, h[2], l[2]);
        q2(v[g].w * inv, h[3], l[3]);
        size_t o4 = (size_t)row * (DD/4) + lane + g * 32;
        ((char4*)hi)[o4] = *(char4*)h;
        ((char4*)lo)[o4] = *(char4*)l;
    }
}

// per-column max of W (column = d), scale out
__global__ __launch_bounds__(256) void colmax(const float* __restrict__ W,
                                              float* __restrict__ sc)
{
    int d = blockIdx.x * 256 + threadIdx.x;
    float mx = 0.f;
    for (int o = 0; o < DD; o++) mx = fmaxf(mx, fabsf(W[(size_t)o * DD + d]));
    sc[d] = mx / QMAX;
}

// transpose + quantize: out[d][o] = W[o][d] limbs, scale per d
__global__ void quantT(const float* __restrict__ W, const float* __restrict__ sc,
                       int8_t* __restrict__ hi, int8_t* __restrict__ lo)
{
    __shared__ float t[32][33];
    int bx = blockIdx.x * 32, by = blockIdx.y * 32;
    int tx = threadIdx.x, ty = threadIdx.y;
    #pragma unroll
    for (int i = 0; i < 4; i++)
        t[ty + 8*i][tx] = W[(size_t)(by + ty + 8*i) * DD + bx + tx];
    __syncthreads();
    #pragma unroll
    for (int i = 0; i < 4; i++) {
        int d = bx + ty + 8*i;
        float s = sc[d];
        float inv = (s > 0.f) ? 1.f / s : 0.f;
        int8_t h, l;
        q2(t[tx][ty + 8*i] * inv, h, l);
        size_t o = (size_t)d * DD + by + tx;
        hi[o] = h; lo[o] = l;
    }
}

// ---------------------------------------------------------------------------
// IMMA GEMM: C[m,o] = sa[m]*sb[o]*(16384*HH + 128*(HL+LH)).
// CTA 128x128, 8 warps (32x64 tiles), 64 int8 k per stage, double-buffered.
// scatter=1: write split-bf16 scattered [b,n,p,h] (QKV); 0: fp32 row-major.
// ---------------------------------------------------------------------------
#define ROWB 80                  // 64 int8 + 16 pad
#define MATB (128*ROWB)
#define STAGEB (4*MATB)          // Ah, Al, Bh, Bl

__global__ __launch_bounds__(256, 1) void gemm_imma(
    const int8_t* __restrict__ Ah8, const int8_t* __restrict__ Al8,
    const int8_t* __restrict__ B0h, const int8_t* __restrict__ B0l,
    const int8_t* __restrict__ B1h, const int8_t* __restrict__ B1l,
    const int8_t* __restrict__ B2h, const int8_t* __restrict__ B2l,
    const float* __restrict__ sa,
    const float* __restrict__ sb0, const float* __restrict__ sb1, const float* __restrict__ sb2,
    float* __restrict__ of,
    __nv_bfloat16* __restrict__ s0h, __nv_bfloat16* __restrict__ s0l,
    __nv_bfloat16* __restrict__ s1h, __nv_bfloat16* __restrict__ s1l,
    __nv_bfloat16* __restrict__ s2h, __nv_bfloat16* __restrict__ s2l,
    int scatter)
{
    extern __shared__ char smem[];
    const int tid = threadIdx.x, lane = tid & 31, wid = tid >> 5;
    const int wm = wid & 3, wn = wid >> 2;
    const int n0 = blockIdx.x * 128, m0 = blockIdx.y * 128, z = blockIdx.z;
    const int8_t* Bh8 = (z == 0) ? B0h : (z == 1) ? B1h : B2h;
    const int8_t* Bl8 = (z == 0) ? B0l : (z == 1) ? B1l : B2l;
    const float* sb = (z == 0) ? sb0 : (z == 1) ? sb1 : sb2;
    __nv_bfloat16* outh = (z == 0) ? s0h : (z == 1) ? s1h : s2h;
    __nv_bfloat16* outl = (z == 0) ? s0l : (z == 1) ? s1l : s2l;
    const float post = (scatter && z == 0) ? QSCALE : 1.0f;

    const int8_t* gsrc[4] = {
        Ah8 + (size_t)m0 * DD, Al8 + (size_t)m0 * DD,
        Bh8 + (size_t)n0 * DD, Bl8 + (size_t)n0 * DD };

    const uint32_t sbase = smem_u32(smem);
    const int lrow = tid >> 2;    // 0..63
    const int lseg = tid & 3;     // 16B segment of 64B row

    int accH[2][8][4], accL[2][8][4];
    #pragma unroll
    for (int t = 0; t < 2; t++)
        #pragma unroll
        for (int j = 0; j < 8; j++)
            #pragma unroll
            for (int x = 0; x < 4; x++) { accH[t][j][x] = 0; accL[t][j][x] = 0; }

    {
        #pragma unroll
        for (int i = 0; i < 8; i++) {
            int mat = i >> 1;
            int r = ((i & 1) << 6) | lrow;
            CP_ASYNC16(sbase + mat * MATB + r * ROWB + lseg * 16,
                       gsrc[mat] + (size_t)r * DD + lseg * 16);
        }
        CP_COMMIT();
    }

    for (int it = 0; it < 16; it++) {
        CP_WAIT0();
        __syncthreads();
        if (it + 1 < 16) {
            int k0 = (it + 1) * 64;
            uint32_t sbn = sbase + ((it + 1) & 1) * STAGEB;
            #pragma unroll
            for (int i = 0; i < 8; i++) {
                int mat = i >> 1;
                int r = ((i & 1) << 6) | lrow;
                CP_ASYNC16(sbn + mat * MATB + r * ROWB + lseg * 16,
                           gsrc[mat] + (size_t)r * DD + k0 + lseg * 16);
            }
            CP_COMMIT();
        }

        const uint32_t st = sbase + (it & 1) * STAGEB;
        #pragma unroll
        for (int kh = 0; kh < 2; kh++) {       // two k32 steps per 64B row
            uint32_t ah[2][4], al[2][4], bh[8][2], bl[8][2];
            #pragma unroll
            for (int t = 0; t < 2; t++) {
                int row = wm * 32 + t * 16 + (lane & 15);
                uint32_t off = ((lane >> 4) * 16) + kh * 32;
                LDSM_X4(ah[t], st + 0 * MATB + row * ROWB + off);
                LDSM_X4(al[t], st + 1 * MATB + row * ROWB + off);
            }
            #pragma unroll
            for (int j = 0; j < 8; j++) {
                int row = wn * 64 + j * 8 + (lane & 7);
                uint32_t off = (((lane >> 3) & 1) * 16) + kh * 32;
                LDSM_X2(bh[j], st + 2 * MATB + row * ROWB + off);
                LDSM_X2(bl[j], st + 3 * MATB + row * ROWB + off);
            }
            #pragma unroll
            for (int t = 0; t < 2; t++)
                #pragma unroll
                for (int j = 0; j < 8; j++) {
                    MMA_S8(accH[t][j], ah[t], bh[j]);
                    MMA_S8(accL[t][j], ah[t], bl[j]);
                    MMA_S8(accL[t][j], al[t], bh[j]);
                }
        }
        __syncthreads();
    }

    // epilogue
    const int r0 = lane >> 2, c0 = (lane & 3) * 2;
    float sam[2][2];
    #pragma unroll
    for (int t = 0; t < 2; t++)
        #pragma unroll
        for (int h2 = 0; h2 < 2; h2++)
            sam[t][h2] = __ldg(&sa[m0 + wm * 32 + t * 16 + r0 + h2 * 8]) * post;

    #pragma unroll
    for (int t = 0; t < 2; t++) {
        #pragma unroll
        for (int j = 0; j < 8; j++) {
            int o = n0 + wn * 64 + j * 8 + c0;
            float sb0v = __ldg(&sb[o]), sb1v = __ldg(&sb[o + 1]);
            #pragma unroll
            for (int h2 = 0; h2 < 2; h2++) {
                int m = m0 + wm * 32 + t * 16 + r0 + h2 * 8;
                float f0 = 16384.f * (float)accH[t][j][2*h2]   + 128.f * (float)accL[t][j][2*h2];
                float f1 = 16384.f * (float)accH[t][j][2*h2+1] + 128.f * (float)accL[t][j][2*h2+1];
                float x0 = f0 * sam[t][h2] * sb0v;
                float x1 = f1 * sam[t][h2] * sb1v;
                if (scatter) {
                    int b = m >> 11, p = m & 2047;
                    int n = o >> 6, hh = o & 63;
                    size_t didx = ((size_t)(b * NH + n) * SS + p) * HD + hh;
                    uint32_t hi, lo;
                    split_pack(x0, x1, hi, lo);
                    *(uint32_t*)(outh + didx) = hi;
                    *(uint32_t*)(outl + didx) = lo;
                } else {
                    *(float2*)(of + (size_t)m * DD + o) = make_float2(x0, x1);
                }
            }
        }
    }
}

// ---------------------------------------------------------------------------
// Tensor-core flash attention (causal), split-bf16 3-term, exp2 softmax.
// Writes fp32 output in [b,p,(n,h)] layout.
// ---------------------------------------------------------------------------
#define AROWB 144
#define AMAT  (64*AROWB)
#define ASTG  (4*AMAT)
#define AQB   (128*AROWB)

__global__ __launch_bounds__(256, 1) void attn_mma(
    const __nv_bfloat16* __restrict__ Qh, const __nv_bfloat16* __restrict__ Ql,
    const __nv_bfloat16* __restrict__ Kh, const __nv_bfloat16* __restrict__ Kl,
    const __nv_bfloat16* __restrict__ Vh, const __nv_bfloat16* __restrict__ Vl,
    float* __restrict__ Og)
{
    extern __shared__ char smem[];
    const uint32_t sb = smem_u32(smem);
    const int tid = threadIdx.x, lane = tid & 31, wid = tid >> 5;
    const int qb = (int)gridDim.x - 1 - (int)blockIdx.x;
    const int q0 = qb * 128;
    const int n = blockIdx.y, b = blockIdx.z;
    const size_t base = (size_t)(b * NH + n) * SS * HD;
    const int nt = 2 * qb + 2;
    const uint32_t ST0 = sb + 2 * AQB;

    auto load_tile = [&](int t) {
        uint32_t stb = ST0 + (uint32_t)(t & 1) * ASTG;
        int key0 = t * 64;
        const __nv_bfloat16* ms[4] = {
            Kh + base + (size_t)key0 * HD, Kl + base + (size_t)key0 * HD,
            Vh + base + (size_t)key0 * HD, Vl + base + (size_t)key0 * HD };
        #pragma unroll
        for (int mt = 0; mt < 4; mt++) {
            #pragma unroll
            for (int u = 0; u < 2; u++) {
                int idx = tid + u * 256;
                int row = idx >> 3, seg = idx & 7;
                CP_ASYNC16(stb + mt * AMAT + row * AROWB + seg * 16,
                           ms[mt] + (size_t)row * HD + seg * 8);
            }
        }
    };

    {
        const __nv_bfloat16* qs[2] = { Qh + base + (size_t)q0 * HD, Ql + base + (size_t)q0 * HD };
        #pragma unroll
        for (int mt = 0; mt < 2; mt++) {
            #pragma unroll
            for (int u = 0; u < 4; u++) {
                int idx = tid + u * 256;
                int row = idx >> 3, seg = idx & 7;
                CP_ASYNC16(sb + mt * AQB + row * AROWB + seg * 16,
                           qs[mt] + (size_t)row * HD + seg * 8);
            }
        }
        load_tile(0);
        CP_COMMIT();
        load_tile(1);
        CP_COMMIT();
    }

    CP_WAIT1();
    __syncthreads();

    uint32_t qfh[4][4], qfl[4][4];
    const int qw = wid * 16;
    #pragma unroll
    for (int kh = 0; kh < 4; kh++) {
        uint32_t a = sb + (qw + (lane & 15)) * AROWB + kh * 32 + (lane >> 4) * 16;
        LDSM_X4(qfh[kh], a);
        LDSM_X4(qfl[kh], a + AQB);
    }

    float m0r = -1e30f, m1r = -1e30f, l0r = 0.f, l1r = 0.f;
    float O[8][4];
    #pragma unroll
    for (int j = 0; j < 8; j++)
        #pragma unroll
        for (int x = 0; x < 4; x++) O[j][x] = 0.f;

    const int row0 = q0 + qw + (lane >> 2);
    const int cl = (lane & 3) * 2;

    for (int it = 0; it < nt; it++) {
        const uint32_t stb = ST0 + (uint32_t)(it & 1) * ASTG;

        float S[8][4];
        #pragma unroll
        for (int j = 0; j < 8; j++)
            #pragma unroll
            for (int x = 0; x < 4; x++) S[j][x] = 0.f;

        #pragma unroll
        for (int kh = 0; kh < 4; kh++) {
            uint32_t kbh[4][4], kbl[4][4];
            const int g = lane >> 3, r = lane & 7;
            #pragma unroll
            for (int jp = 0; jp < 4; jp++) {
                uint32_t a = stb + (uint32_t)(((jp * 2 + (g >> 1)) * 8 + r) * AROWB + (g & 1) * 16 + kh * 32);
                LDSM_X4(kbh[jp], a);
                LDSM_X4(kbl[jp], a + AMAT);
            }
            #pragma unroll
            for (int jp = 0; jp < 4; jp++) {
                MMA_BF16(S[2*jp],   qfh[kh], kbh[jp]);
                MMA_BF16(S[2*jp],   qfh[kh], kbl[jp]);
                MMA_BF16(S[2*jp],   qfl[kh], kbh[jp]);
                MMA_BF16(S[2*jp+1], qfh[kh], kbh[jp]+2);
                MMA_BF16(S[2*jp+1], qfh[kh], kbl[jp]+2);
                MMA_BF16(S[2*jp+1], qfl[kh], kbh[jp]+2);
            }
        }

        if (it >= nt - 2) {
            const int kbase = it * 64 + cl;
            #pragma unroll
            for (int j = 0; j < 8; j++) {
                int c = kbase + j * 8;
                if (c     > row0)     S[j][0] = -1e30f;
                if (c + 1 > row0)     S[j][1] = -1e30f;
                if (c     > row0 + 8) S[j][2] = -1e30f;
                if (c + 1 > row0 + 8) S[j][3] = -1e30f;
            }
        }

        float mn0 = m0r, mn1 = m1r;
        #pragma unroll
        for (int j = 0; j < 8; j++) {
            mn0 = fmaxf(mn0, fmaxf(S[j][0], S[j][1]));
            mn1 = fmaxf(mn1, fmaxf(S[j][2], S[j][3]));
        }
        mn0 = fmaxf(mn0, __shfl_xor_sync(0xffffffffu, mn0, 1));
        mn0 = fmaxf(mn0, __shfl_xor_sync(0xffffffffu, mn0, 2));
        mn1 = fmaxf(mn1, __shfl_xor_sync(0xffffffffu, mn1, 1));
        mn1 = fmaxf(mn1, __shfl_xor_sync(0xffffffffu, mn1, 2));

        float c0 = ex2f(m0r - mn0), c1 = ex2f(m1r - mn1);
        l0r *= c0; l1r *= c1;
        #pragma unroll
        for (int j = 0; j < 8; j++) {
            O[j][0] *= c0; O[j][1] *= c0; O[j][2] *= c1; O[j][3] *= c1;
        }
        m0r = mn0; m1r = mn1;

        uint32_t ph[4][4], pl[4][4];
        float s0 = 0.f, s1 = 0.f;
        #pragma unroll
        for (int j = 0; j < 8; j++) {
            float p0 = ex2f(S[j][0] - mn0), p1 = ex2f(S[j][1] - mn0);
            float p2 = ex2f(S[j][2] - mn1), p3 = ex2f(S[j][3] - mn1);
            s0 += p0 + p1; s1 += p2 + p3;
            int kk = j >> 1, i0 = (j & 1) * 2;
            split_pack(p0, p1, ph[kk][i0],   pl[kk][i0]);
            split_pack(p2, p3, ph[kk][i0+1], pl[kk][i0+1]);
        }
        s0 += __shfl_xor_sync(0xffffffffu, s0, 1);
        s0 += __shfl_xor_sync(0xffffffffu, s0, 2);
        s1 += __shfl_xor_sync(0xffffffffu, s1, 1);
        s1 += __shfl_xor_sync(0xffffffffu, s1, 2);
        l0r += s0; l1r += s1;

        {
            const int g = lane >> 3, r = lane & 7;
            #pragma unroll
            for (int kk = 0; kk < 4; kk++) {
                #pragma unroll
                for (int jn = 0; jn < 4; jn++) {
                    uint32_t vbh[4], vbl[4];
                    uint32_t a = stb + 2 * AMAT
                        + (uint32_t)((kk * 16 + ((g & 1) << 3) + r) * AROWB + (2 * jn + (g >> 1)) * 16);
                    LDSM_X4T(vbh, a);
                    LDSM_X4T(vbl, a + AMAT);
                    MMA_BF16(O[2*jn],   ph[kk], vbh);
                    MMA_BF16(O[2*jn],   ph[kk], vbl);
                    MMA_BF16(O[2*jn],   pl[kk], vbh);
                    MMA_BF16(O[2*jn+1], ph[kk], vbh+2);
                    MMA_BF16(O[2*jn+1], ph[kk], vbl+2);
                    MMA_BF16(O[2*jn+1], pl[kk], vbh+2);
                }
            }
        }

        __syncthreads();
        int nx = it + 2;
        if (nx < nt) { load_tile(nx); CP_COMMIT(); }
        if (it + 1 < nt) {
            if (nx < nt) CP_WAIT1(); else CP_WAIT0();
            __syncthreads();
        }
    }

    float inv0 = 1.f / l0r, inv1 = 1.f / l1r;
    size_t orow0 = ((size_t)(b * SS + row0)) * DD + n * HD;
    size_t orow1 = orow0 + (size_t)8 * DD;
    #pragma unroll
    for (int nb = 0; nb < 8; nb++) {
        int d = nb * 8 + cl;
        *(float2*)(Og + orow0 + d) = make_float2(O[nb][0] * inv0, O[nb][1] * inv0);
        *(float2*)(Og + orow1 + d) = make_float2(O[nb][2] * inv1, O[nb][3] * inv1);
    }
}

// ---------------------------------------------------------------------------
extern "C" void kernel_launch(void* const* d_in, const int* in_sizes, int n_in,
                              void* d_out, int out_size)
{
    const float* residual = (const float*)d_in[0];
    const float* W_Q = (const float*)d_in[1];
    const float* W_K = (const float*)d_in[2];
    const float* W_V = (const float*)d_in[3];
    const float* W_O = (const float*)d_in[4];
    float* out = (float*)d_out;

    int8_t *a8h, *a8l, *a28h, *a28l;
    int8_t *wq8h, *wq8l, *wk8h, *wk8l, *wv8h, *wv8l, *wo8h, *wo8l;
    float *sA, *sA2, *sWQ, *sWK, *sWV, *sWO, *attn;
    __nv_bfloat16 *qh, *ql, *kh, *kl, *vh, *vl;
    cudaGetSymbolAddress((void**)&a8h,  g_A8h);   cudaGetSymbolAddress((void**)&a8l,  g_A8l);
    cudaGetSymbolAddress((void**)&a28h, g_A28h);  cudaGetSymbolAddress((void**)&a28l, g_A28l);
    cudaGetSymbolAddress((void**)&wq8h, g_WQ8h);  cudaGetSymbolAddress((void**)&wq8l, g_WQ8l);
    cudaGetSymbolAddress((void**)&wk8h, g_WK8h);  cudaGetSymbolAddress((void**)&wk8l, g_WK8l);
    cudaGetSymbolAddress((void**)&wv8h, g_WV8h);  cudaGetSymbolAddress((void**)&wv8l, g_WV8l);
    cudaGetSymbolAddress((void**)&wo8h, g_WO8h);  cudaGetSymbolAddress((void**)&wo8l, g_WO8l);
    cudaGetSymbolAddress((void**)&sA,  g_sA);   cudaGetSymbolAddress((void**)&sA2, g_sA2);
    cudaGetSymbolAddress((void**)&sWQ, g_sWQ);  cudaGetSymbolAddress((void**)&sWK, g_sWK);
    cudaGetSymbolAddress((void**)&sWV, g_sWV);  cudaGetSymbolAddress((void**)&sWO, g_sWO);
    cudaGetSymbolAddress((void**)&attn, g_attn);
    cudaGetSymbolAddress((void**)&qh, g_Qhi);   cudaGetSymbolAddress((void**)&ql, g_Qlo);
    cudaGetSymbolAddress((void**)&kh, g_Khi);   cudaGetSymbolAddress((void**)&kl, g_Klo);
    cudaGetSymbolAddress((void**)&vh, g_Vhi);   cudaGetSymbolAddress((void**)&vl, g_Vlo);

    const int GSMEM = 2 * STAGEB;                  // 81920
    const int ASMEM = 2 * AQB + 2 * ASTG;          // 110592
    cudaFuncSetAttribute(gemm_imma, cudaFuncAttributeMaxDynamicSharedMemorySize, GSMEM);
    cudaFuncSetAttribute(attn_mma,  cudaFuncAttributeMaxDynamicSharedMemorySize, ASMEM);

    quant_rows<<<MM/8, 256>>>(residual, a8h, a8l, sA);
    quant_rows<<<DD/8, 256>>>(W_Q, wq8h, wq8l, sWQ);
    quant_rows<<<DD/8, 256>>>(W_K, wk8h, wk8l, sWK);
    quant_rows<<<DD/8, 256>>>(W_V, wv8h, wv8l, sWV);
    colmax<<<DD/256, 256>>>(W_O, sWO);
    quantT<<<dim3(32,32), dim3(32,8)>>>(W_O, sWO, wo8h, wo8l);

    // QKV projections -> split bf16 scattered [b,n,p,h]; Q pre-scaled
    gemm_imma<<<dim3(8, 32, 3), 256, GSMEM>>>(a8h, a8l,
        wq8h, wq8l, wk8h, wk8l, wv8h, wv8l,
        sA, sWQ, sWK, sWV,
        nullptr, qh, ql, kh, kl, vh, vl, 1);

    // flash attention -> fp32 [b,p,(n,h)]
    attn_mma<<<dim3(SS/128, NH, BB), 256, ASMEM>>>(qh, ql, kh, kl, vh, vl, attn);

    // quantize attention output, then O-projection (fp32 out)
    quant_rows<<<MM/8, 256>>>(attn, a28h, a28l, sA2);
    gemm_imma<<<dim3(8, 32, 1), 256, GSMEM>>>(a28h, a28l,
        wo8h, wo8l, wo8h, wo8l, wo8h, wo8l,
        sA2, sWO, sWO, sWO,
        out, nullptr, nullptr, nullptr, nullptr, nullptr, nullptr, 0);
}

// round 7
// speedup vs baseline: 2.3002x; 2.3002x over previous
#include <cuda_runtime.h>
#include <cuda_bf16.h>
#include <cuda_fp16.h>
#include <cstdint>
#include <math.h>

// Problem constants
#define BB 2
#define SS 2048
#define DD 1024
#define NH 16
#define HD 64
#define MM (BB*SS)      // 4096
#define QSCALE 0.18033688011112042f   // 0.125 * log2(e)

// ---------------------------------------------------------------------------
// Scratch (device globals)
// ---------------------------------------------------------------------------
__device__ __align__(16) __nv_bfloat16 g_Ahi[MM*DD],  g_Alo[MM*DD];     // residual split
__device__ __align__(16) __nv_bfloat16 g_A2hi[MM*DD], g_A2lo[MM*DD];    // attn out split
__device__ __align__(16) __nv_bfloat16 g_WQhi[DD*DD], g_WQlo[DD*DD];
__device__ __align__(16) __nv_bfloat16 g_WKhi[DD*DD], g_WKlo[DD*DD];
__device__ __align__(16) __nv_bfloat16 g_WVhi[DD*DD], g_WVlo[DD*DD];
__device__ __align__(16) __nv_bfloat16 g_WOhi[DD*DD], g_WOlo[DD*DD];    // transposed W_O
__device__ __align__(16) __half g_Q16[BB*NH*SS*HD];
__device__ __align__(16) __half g_K16[BB*NH*SS*HD];
__device__ __align__(16) __half g_V16[BB*NH*SS*HD];

// ---------------------------------------------------------------------------
// helpers
// ---------------------------------------------------------------------------
__device__ __forceinline__ uint32_t smem_u32(const void* p) {
    uint32_t a;
    asm("{ .reg .u64 t; cvta.to.shared.u64 t, %1; cvt.u32.u64 %0, t; }" : "=r"(a) : "l"(p));
    return a;
}
#define LDSM_X4(r, a) asm volatile("ldmatrix.sync.aligned.m8n8.x4.shared.b16 {%0,%1,%2,%3}, [%4];" \
  : "=r"((r)[0]),"=r"((r)[1]),"=r"((r)[2]),"=r"((r)[3]) : "r"(a))
#define LDSM_X4T(r, a) asm volatile("ldmatrix.sync.aligned.m8n8.x4.trans.shared.b16 {%0,%1,%2,%3}, [%4];" \
  : "=r"((r)[0]),"=r"((r)[1]),"=r"((r)[2]),"=r"((r)[3]) : "r"(a))
#define LDSM_X2(r, a) asm volatile("ldmatrix.sync.aligned.m8n8.x2.shared.b16 {%0,%1}, [%2];" \
  : "=r"((r)[0]),"=r"((r)[1]) : "r"(a))
#define MMA_BF16(d, a, b) asm volatile( \
  "mma.sync.aligned.m16n8k16.row.col.f32.bf16.bf16.f32 {%0,%1,%2,%3},{%4,%5,%6,%7},{%8,%9},{%0,%1,%2,%3};" \
  : "+f"((d)[0]), "+f"((d)[1]), "+f"((d)[2]), "+f"((d)[3]) \
  : "r"((a)[0]),"r"((a)[1]),"r"((a)[2]),"r"((a)[3]), "r"((b)[0]),"r"((b)[1]))
#define MMA_F16(d, a, b) asm volatile( \
  "mma.sync.aligned.m16n8k16.row.col.f32.f16.f16.f32 {%0,%1,%2,%3},{%4,%5,%6,%7},{%8,%9},{%0,%1,%2,%3};" \
  : "+f"((d)[0]), "+f"((d)[1]), "+f"((d)[2]), "+f"((d)[3]) \
  : "r"((a)[0]),"r"((a)[1]),"r"((a)[2]),"r"((a)[3]), "r"((b)[0]),"r"((b)[1]))
#define CP_ASYNC16(dst, src) asm volatile("cp.async.cg.shared.global [%0], [%1], 16;" :: "r"(dst), "l"(src))
#define CP_COMMIT() asm volatile("cp.async.commit_group;" ::: "memory")
#define CP_WAIT0()  asm volatile("cp.async.wait_group 0;" ::: "memory")
#define CP_WAIT1()  asm volatile("cp.async.wait_group 1;" ::: "memory")

__device__ __forceinline__ float ex2f(float x) {
    float y; asm("ex2.approx.ftz.f32 %0, %1;" : "=f"(y) : "f"(x)); return y;
}
__device__ __forceinline__ uint32_t pack_h2(float a, float b) {
    uint32_t u;
    asm("{ .reg .f16 lo, hi; cvt.rn.f16.f32 lo, %1; cvt.rn.f16.f32 hi, %2; mov.b32 %0, {lo, hi}; }"
        : "=r"(u) : "f"(a), "f"(b));
    return u;
}
__device__ __forceinline__ uint32_t packbf(__nv_bfloat16 a, __nv_bfloat16 b) {
    return (uint32_t)__bfloat16_as_ushort(a) | ((uint32_t)__bfloat16_as_ushort(b) << 16);
}
__device__ __forceinline__ void split_pack(float x0, float x1, uint32_t& hi, uint32_t& lo) {
    __nv_bfloat16 h0 = __float2bfloat16(x0), h1 = __float2bfloat16(x1);
    hi = packbf(h0, h1);
    __nv_bfloat16 g0 = __float2bfloat16(x0 - __bfloat162float(h0));
    __nv_bfloat16 g1 = __float2bfloat16(x1 - __bfloat162float(h1));
    lo = packbf(g0, g1);
}

// ---------------------------------------------------------------------------
// split fp32 -> bf16 hi/lo (row-major)
// ---------------------------------------------------------------------------
__global__ __launch_bounds__(256) void split2(const float* __restrict__ src,
                                              __nv_bfloat16* __restrict__ hi,
                                              __nv_bfloat16* __restrict__ lo)
{
    int idx = blockIdx.x * 256 + threadIdx.x;
    const float4* s = (const float4*)src + (size_t)idx * 2;
    float4 a0 = s[0], a1 = s[1];
    float av[8] = {a0.x, a0.y, a0.z, a0.w, a1.x, a1.y, a1.z, a1.w};
    __nv_bfloat16 h[8], l[8];
    #pragma unroll
    for (int j = 0; j < 8; j++) {
        h[j] = __float2bfloat16(av[j]);
        l[j] = __float2bfloat16(av[j] - __bfloat162float(h[j]));
    }
    ((uint4*)hi)[idx] = *(uint4*)h;
    ((uint4*)lo)[idx] = *(uint4*)l;
}

// transpose + split: out[d][o] = W[o][d]
__global__ void splitT(const float* __restrict__ W,
                       __nv_bfloat16* __restrict__ hi, __nv_bfloat16* __restrict__ lo)
{
    __shared__ float t[32][33];
    int bx = blockIdx.x * 32, by = blockIdx.y * 32;
    int tx = threadIdx.x, ty = threadIdx.y;
    #pragma unroll
    for (int i = 0; i < 4; i++)
        t[ty + 8*i][tx] = W[(size_t)(by + ty + 8*i) * DD + bx + tx];
    __syncthreads();
    #pragma unroll
    for (int i = 0; i < 4; i++) {
        float v = t[tx][ty + 8*i];
        __nv_bfloat16 h = __float2bfloat16(v);
        __nv_bfloat16 l = __float2bfloat16(v - __bfloat162float(h));
        size_t o = (size_t)(bx + ty + 8*i) * DD + by + tx;
        hi[o] = h; lo[o] = l;
    }
}

// ---------------------------------------------------------------------------
// HMMA GEMM: C[m,o] = sum_d A[m,d]*B[o,d], 3-term split bf16.
// scatter=1: write fp16 scattered to [b,n,p,h] (QKV path, Q pre-scaled)
// scatter=0: write fp32 row-major (O-projection)
// ---------------------------------------------------------------------------
#define ROWB 80
#define MATB (128*ROWB)
#define STAGEB (4*MATB)

__global__ __launch_bounds__(256, 1) void gemm_mma(
    const __nv_bfloat16* __restrict__ Ahi, const __nv_bfloat16* __restrict__ Alo,
    const __nv_bfloat16* __restrict__ B0hi, const __nv_bfloat16* __restrict__ B0lo,
    const __nv_bfloat16* __restrict__ B1hi, const __nv_bfloat16* __restrict__ B1lo,
    const __nv_bfloat16* __restrict__ B2hi, const __nv_bfloat16* __restrict__ B2lo,
    float* __restrict__ of,
    __half* __restrict__ q16, __half* __restrict__ k16, __half* __restrict__ v16,
    int scatter)
{
    extern __shared__ char smem[];
    const int tid = threadIdx.x, lane = tid & 31, wid = tid >> 5;
    const int wm = wid & 3, wn = wid >> 2;
    const int n0 = blockIdx.x * 128, m0 = blockIdx.y * 128, z = blockIdx.z;
    const __nv_bfloat16* Bhi = (z == 0) ? B0hi : (z == 1) ? B1hi : B2hi;
    const __nv_bfloat16* Blo = (z == 0) ? B0lo : (z == 1) ? B1lo : B2lo;
    __half* out16 = (z == 0) ? q16 : (z == 1) ? k16 : v16;
    const float scalef = (scatter && z == 0) ? QSCALE : 1.0f;

    const __nv_bfloat16* gsrc[4] = {
        Ahi + (size_t)m0 * DD, Alo + (size_t)m0 * DD,
        Bhi + (size_t)n0 * DD, Blo + (size_t)n0 * DD };

    const uint32_t sbase = smem_u32(smem);
    const int lrow = tid >> 2;
    const int lseg = tid & 3;

    float acc[2][8][4];
    #pragma unroll
    for (int t = 0; t < 2; t++)
        #pragma unroll
        for (int j = 0; j < 8; j++)
            #pragma unroll
            for (int x = 0; x < 4; x++) acc[t][j][x] = 0.f;

    {
        #pragma unroll
        for (int i = 0; i < 8; i++) {
            int mat = i >> 1;
            int r = ((i & 1) << 6) | lrow;
            const __nv_bfloat16* g = gsrc[mat] + (size_t)r * DD + lseg * 8;
            CP_ASYNC16(sbase + mat * MATB + r * ROWB + lseg * 16, g);
        }
        CP_COMMIT();
    }

    for (int it = 0; it < 32; it++) {
        CP_WAIT0();
        __syncthreads();
        if (it + 1 < 32) {
            int k0 = (it + 1) * 32;
            uint32_t sb = sbase + ((it + 1) & 1) * STAGEB;
            #pragma unroll
            for (int i = 0; i < 8; i++) {
                int mat = i >> 1;
                int r = ((i & 1) << 6) | lrow;
                const __nv_bfloat16* g = gsrc[mat] + (size_t)r * DD + k0 + lseg * 8;
                CP_ASYNC16(sb + mat * MATB + r * ROWB + lseg * 16, g);
            }
            CP_COMMIT();
        }

        const uint32_t st = sbase + (it & 1) * STAGEB;
        #pragma unroll
        for (int kh = 0; kh < 2; kh++) {
            uint32_t ah[2][4], al[2][4], bh[8][2], bl[8][2];
            #pragma unroll
            for (int t = 0; t < 2; t++) {
                int row = wm * 32 + t * 16 + (lane & 15);
                uint32_t off = ((lane >> 4) * 16) + kh * 32;
                LDSM_X4(ah[t], st + 0 * MATB + row * ROWB + off);
                LDSM_X4(al[t], st + 1 * MATB + row * ROWB + off);
            }
            #pragma unroll
            for (int j = 0; j < 8; j++) {
                int row = wn * 64 + j * 8 + (lane & 7);
                uint32_t off = (((lane >> 3) & 1) * 16) + kh * 32;
                LDSM_X2(bh[j], st + 2 * MATB + row * ROWB + off);
                LDSM_X2(bl[j], st + 3 * MATB + row * ROWB + off);
            }
            #pragma unroll
            for (int t = 0; t < 2; t++)
                #pragma unroll
                for (int j = 0; j < 8; j++) {
                    MMA_BF16(acc[t][j], ah[t], bh[j]);
                    MMA_BF16(acc[t][j], ah[t], bl[j]);
                    MMA_BF16(acc[t][j], al[t], bh[j]);
                }
        }
        __syncthreads();
    }

    // epilogue
    const int r0 = lane >> 2, c0 = (lane & 3) * 2;
    #pragma unroll
    for (int t = 0; t < 2; t++) {
        #pragma unroll
        for (int j = 0; j < 8; j++) {
            int o = n0 + wn * 64 + j * 8 + c0;
            #pragma unroll
            for (int h2 = 0; h2 < 2; h2++) {
                int m = m0 + wm * 32 + t * 16 + r0 + h2 * 8;
                float x0 = acc[t][j][2*h2] * scalef, x1 = acc[t][j][2*h2+1] * scalef;
                if (scatter) {
                    int b = m >> 11, p = m & 2047;
                    int n = o >> 6, hh = o & 63;
                    size_t didx = ((size_t)(b * NH + n) * SS + p) * HD + hh;
                    *(uint32_t*)(out16 + didx) = pack_h2(x0, x1);
                } else {
                    *(float2*)(of + (size_t)m * DD + o) = make_float2(x0, x1);
                }
            }
        }
    }
}

// ---------------------------------------------------------------------------
// Tensor-core flash attention (causal), 1-term fp16, exp2-domain softmax.
// CTA: 128 q-rows, 8 warps x 16 rows. K-tiles of 64, double-buffered.
// Writes split-bf16 output in [b,p,(n,h)] layout for the O-projection GEMM.
// ---------------------------------------------------------------------------
#define AROWB 144               // 64 fp16 (128B) + 16B pad
#define AMAT  (64*AROWB)        // 9216
#define ASTG  (2*AMAT)          // 18432: K, V
#define AQB   (128*AROWB)       // 18432

__global__ __launch_bounds__(256, 1) void attn_mma(
    const __half* __restrict__ Qg, const __half* __restrict__ Kg,
    const __half* __restrict__ Vg,
    __nv_bfloat16* __restrict__ Oh, __nv_bfloat16* __restrict__ Ol)
{
    extern __shared__ char smem[];
    const uint32_t sb = smem_u32(smem);
    const int tid = threadIdx.x, lane = tid & 31, wid = tid >> 5;
    const int qb = (int)gridDim.x - 1 - (int)blockIdx.x;   // long CTAs first
    const int q0 = qb * 128;
    const int n = blockIdx.y, b = blockIdx.z;
    const size_t base = (size_t)(b * NH + n) * SS * HD;
    const int nt = 2 * qb + 2;
    const uint32_t ST0 = sb + AQB;

    auto load_tile = [&](int t) {
        uint32_t stb = ST0 + (uint32_t)(t & 1) * ASTG;
        int key0 = t * 64;
        const __half* ms[2] = { Kg + base + (size_t)key0 * HD, Vg + base + (size_t)key0 * HD };
        #pragma unroll
        for (int mt = 0; mt < 2; mt++) {
            #pragma unroll
            for (int u = 0; u < 2; u++) {
                int idx = tid + u * 256;     // 0..511
                int row = idx >> 3, seg = idx & 7;
                CP_ASYNC16(stb + mt * AMAT + row * AROWB + seg * 16,
                           ms[mt] + (size_t)row * HD + seg * 8);
            }
        }
    };

    // Q load (grouped with tile 0)
    {
        const __half* qs = Qg + base + (size_t)q0 * HD;
        #pragma unroll
        for (int u = 0; u < 4; u++) {
            int idx = tid + u * 256;         // 0..1023
            int row = idx >> 3, seg = idx & 7;
            CP_ASYNC16(sb + row * AROWB + seg * 16, qs + (size_t)row * HD + seg * 8);
        }
        load_tile(0);
        CP_COMMIT();
        load_tile(1);
        CP_COMMIT();
    }

    CP_WAIT1();
    __syncthreads();

    // Q fragments (registers, persist)
    uint32_t qf[4][4];
    const int qw = wid * 16;
    #pragma unroll
    for (int kh = 0; kh < 4; kh++) {
        uint32_t a = sb + (qw + (lane & 15)) * AROWB + kh * 32 + (lane >> 4) * 16;
        LDSM_X4(qf[kh], a);
    }

    float m0r = -1e30f, m1r = -1e30f, l0r = 0.f, l1r = 0.f;
    float O[8][4];
    #pragma unroll
    for (int j = 0; j < 8; j++)
        #pragma unroll
        for (int x = 0; x < 4; x++) O[j][x] = 0.f;

    const int row0 = q0 + qw + (lane >> 2);
    const int cl = (lane & 3) * 2;

    for (int it = 0; it < nt; it++) {
        const uint32_t stb = ST0 + (uint32_t)(it & 1) * ASTG;

        // ---- S = Q K^T (1-term fp16)
        float S[8][4];
        #pragma unroll
        for (int j = 0; j < 8; j++)
            #pragma unroll
            for (int x = 0; x < 4; x++) S[j][x] = 0.f;

        #pragma unroll
        for (int kh = 0; kh < 4; kh++) {
            uint32_t kb[4][4];
            const int g = lane >> 3, r = lane & 7;
            #pragma unroll
            for (int jp = 0; jp < 4; jp++) {
                uint32_t a = stb + (uint32_t)(((jp * 2 + (g >> 1)) * 8 + r) * AROWB + (g & 1) * 16 + kh * 32);
                LDSM_X4(kb[jp], a);
            }
            #pragma unroll
            for (int jp = 0; jp < 4; jp++) {
                MMA_F16(S[2*jp],   qf[kh], kb[jp]);
                MMA_F16(S[2*jp+1], qf[kh], kb[jp]+2);
            }
        }

        // ---- causal mask (near diagonal only)
        if (it >= nt - 2) {
            const int kbase = it * 64 + cl;
            #pragma unroll
            for (int j = 0; j < 8; j++) {
                int c = kbase + j * 8;
                if (c     > row0)     S[j][0] = -1e30f;
                if (c + 1 > row0)     S[j][1] = -1e30f;
                if (c     > row0 + 8) S[j][2] = -1e30f;
                if (c + 1 > row0 + 8) S[j][3] = -1e30f;
            }
        }

        // ---- online softmax (log2 domain)
        float mn0 = m0r, mn1 = m1r;
        #pragma unroll
        for (int j = 0; j < 8; j++) {
            mn0 = fmaxf(mn0, fmaxf(S[j][0], S[j][1]));
            mn1 = fmaxf(mn1, fmaxf(S[j][2], S[j][3]));
        }
        mn0 = fmaxf(mn0, __shfl_xor_sync(0xffffffffu, mn0, 1));
        mn0 = fmaxf(mn0, __shfl_xor_sync(0xffffffffu, mn0, 2));
        mn1 = fmaxf(mn1, __shfl_xor_sync(0xffffffffu, mn1, 1));
        mn1 = fmaxf(mn1, __shfl_xor_sync(0xffffffffu, mn1, 2));

        float c0 = ex2f(m0r - mn0), c1 = ex2f(m1r - mn1);
        l0r *= c0; l1r *= c1;
        #pragma unroll
        for (int j = 0; j < 8; j++) {
            O[j][0] *= c0; O[j][1] *= c0; O[j][2] *= c1; O[j][3] *= c1;
        }
        m0r = mn0; m1r = mn1;

        uint32_t ph[4][4];
        float s0 = 0.f, s1 = 0.f;
        #pragma unroll
        for (int j = 0; j < 8; j++) {
            float p0 = ex2f(S[j][0] - mn0), p1 = ex2f(S[j][1] - mn0);
            float p2 = ex2f(S[j][2] - mn1), p3 = ex2f(S[j][3] - mn1);
            s0 += p0 + p1; s1 += p2 + p3;
            int kk = j >> 1, i0 = (j & 1) * 2;
            ph[kk][i0]   = pack_h2(p0, p1);
            ph[kk][i0+1] = pack_h2(p2, p3);
        }
        s0 += __shfl_xor_sync(0xffffffffu, s0, 1);
        s0 += __shfl_xor_sync(0xffffffffu, s0, 2);
        s1 += __shfl_xor_sync(0xffffffffu, s1, 1);
        s1 += __shfl_xor_sync(0xffffffffu, s1, 2);
        l0r += s0; l1r += s1;

        // ---- O += P V (1-term fp16)
        {
            const int g = lane >> 3, r = lane & 7;
            #pragma unroll
            for (int kk = 0; kk < 4; kk++) {
                #pragma unroll
                for (int jn = 0; jn < 4; jn++) {
                    uint32_t vb[4];
                    uint32_t a = stb + AMAT
                        + (uint32_t)((kk * 16 + ((g & 1) << 3) + r) * AROWB + (2 * jn + (g >> 1)) * 16);
                    LDSM_X4T(vb, a);
                    MMA_F16(O[2*jn],   ph[kk], vb);
                    MMA_F16(O[2*jn+1], ph[kk], vb+2);
                }
            }
        }

        __syncthreads();
        int nx = it + 2;
        if (nx < nt) { load_tile(nx); CP_COMMIT(); }
        if (it + 1 < nt) {
            if (nx < nt) CP_WAIT1(); else CP_WAIT0();
            __syncthreads();
        }
    }

    // ---- write split-bf16 output: rows (b, q), cols n*64 + hd
    float inv0 = 1.f / l0r, inv1 = 1.f / l1r;
    size_t orow0 = ((size_t)(b * SS + row0)) * DD + n * HD;
    size_t orow1 = orow0 + (size_t)8 * DD;
    #pragma unroll
    for (int nb = 0; nb < 8; nb++) {
        int d = nb * 8 + cl;
        uint32_t hi, lo;
        split_pack(O[nb][0] * inv0, O[nb][1] * inv0, hi, lo);
        *(uint32_t*)(Oh + orow0 + d) = hi;
        *(uint32_t*)(Ol + orow0 + d) = lo;
        split_pack(O[nb][2] * inv1, O[nb][3] * inv1, hi, lo);
        *(uint32_t*)(Oh + orow1 + d) = hi;
        *(uint32_t*)(Ol + orow1 + d) = lo;
    }
}

// ---------------------------------------------------------------------------
extern "C" void kernel_launch(void* const* d_in, const int* in_sizes, int n_in,
                              void* d_out, int out_size)
{
    const float* residual = (const float*)d_in[0];
    const float* W_Q = (const float*)d_in[1];
    const float* W_K = (const float*)d_in[2];
    const float* W_V = (const float*)d_in[3];
    const float* W_O = (const float*)d_in[4];
    float* out = (float*)d_out;

    __nv_bfloat16 *ahi, *alo, *a2hi, *a2lo;
    __nv_bfloat16 *wqh, *wql, *wkh, *wkl, *wvh, *wvl, *woh, *wol;
    __half *q16, *k16, *v16;
    cudaGetSymbolAddress((void**)&ahi,  g_Ahi);
    cudaGetSymbolAddress((void**)&alo,  g_Alo);
    cudaGetSymbolAddress((void**)&a2hi, g_A2hi);
    cudaGetSymbolAddress((void**)&a2lo, g_A2lo);
    cudaGetSymbolAddress((void**)&wqh,  g_WQhi);
    cudaGetSymbolAddress((void**)&wql,  g_WQlo);
    cudaGetSymbolAddress((void**)&wkh,  g_WKhi);
    cudaGetSymbolAddress((void**)&wkl,  g_WKlo);
    cudaGetSymbolAddress((void**)&wvh,  g_WVhi);
    cudaGetSymbolAddress((void**)&wvl,  g_WVlo);
    cudaGetSymbolAddress((void**)&woh,  g_WOhi);
    cudaGetSymbolAddress((void**)&wol,  g_WOlo);
    cudaGetSymbolAddress((void**)&q16,  g_Q16);
    cudaGetSymbolAddress((void**)&k16,  g_K16);
    cudaGetSymbolAddress((void**)&v16,  g_V16);

    const int GSMEM = 2 * STAGEB;              // 81920
    const int ASMEM = AQB + 2 * ASTG;          // 55296
    cudaFuncSetAttribute(gemm_mma, cudaFuncAttributeMaxDynamicSharedMemorySize, GSMEM);
    cudaFuncSetAttribute(attn_mma, cudaFuncAttributeMaxDynamicSharedMemorySize, ASMEM);

    split2<<<MM*DD/8/256, 256>>>(residual, ahi, alo);
    split2<<<DD*DD/8/256, 256>>>(W_Q, wqh, wql);
    split2<<<DD*DD/8/256, 256>>>(W_K, wkh, wkl);
    split2<<<DD*DD/8/256, 256>>>(W_V, wvh, wvl);
    splitT<<<dim3(32,32), dim3(32,8)>>>(W_O, woh, wol);

    // QKV projections -> fp16, scattered [b,n,p,h]; Q pre-scaled
    gemm_mma<<<dim3(8, 32, 3), 256, GSMEM>>>(ahi, alo,
        wqh, wql, wkh, wkl, wvh, wvl,
        nullptr, q16, k16, v16, 1);

    // 1-term fp16 flash attention -> split bf16 [b,p,(n,h)]
    attn_mma<<<dim3(SS/128, NH, BB), 256, ASMEM>>>(q16, k16, v16, a2hi, a2lo);

    // output projection (fp32 out)
    gemm_mma<<<dim3(8, 32, 1), 256, GSMEM>>>(a2hi, a2lo,
        woh, wol, woh, wol, woh, wol,
        out, nullptr, nullptr, nullptr, 0);
}

// round 8
// speedup vs baseline: 4.7249x; 2.0541x over previous
#include <cuda_runtime.h>
#include <cuda_bf16.h>
#include <cuda_fp16.h>
#include <cstdint>
#include <math.h>

// Problem constants
#define BB 2
#define SS 2048
#define DD 1024
#define NH 16
#define HD 64
#define MM (BB*SS)      // 4096
#define QSCALE 0.18033688011112042f   // 0.125 * log2(e)

// ---------------------------------------------------------------------------
// Scratch (device globals)
// ---------------------------------------------------------------------------
__device__ __align__(16) __half g_A16[MM*DD];       // residual fp16
__device__ __align__(16) __half g_A216[MM*DD];      // attn out fp16
__device__ __align__(16) __half g_WQ16[DD*DD];
__device__ __align__(16) __half g_WK16[DD*DD];
__device__ __align__(16) __half g_WV16[DD*DD];
__device__ __align__(16) __half g_WO16[DD*DD];      // transposed W_O
__device__ __align__(16) __half g_Q16[BB*NH*SS*HD];
__device__ __align__(16) __half g_K16[BB*NH*SS*HD];
__device__ __align__(16) __half g_V16[BB*NH*SS*HD];

// ---------------------------------------------------------------------------
// helpers
// ---------------------------------------------------------------------------
__device__ __forceinline__ uint32_t smem_u32(const void* p) {
    uint32_t a;
    asm("{ .reg .u64 t; cvta.to.shared.u64 t, %1; cvt.u32.u64 %0, t; }" : "=r"(a) : "l"(p));
    return a;
}
#define LDSM_X4(r, a) asm volatile("ldmatrix.sync.aligned.m8n8.x4.shared.b16 {%0,%1,%2,%3}, [%4];" \
  : "=r"((r)[0]),"=r"((r)[1]),"=r"((r)[2]),"=r"((r)[3]) : "r"(a))
#define LDSM_X4T(r, a) asm volatile("ldmatrix.sync.aligned.m8n8.x4.trans.shared.b16 {%0,%1,%2,%3}, [%4];" \
  : "=r"((r)[0]),"=r"((r)[1]),"=r"((r)[2]),"=r"((r)[3]) : "r"(a))
#define MMA_F16(d, a, b) asm volatile( \
  "mma.sync.aligned.m16n8k16.row.col.f32.f16.f16.f32 {%0,%1,%2,%3},{%4,%5,%6,%7},{%8,%9},{%0,%1,%2,%3};" \
  : "+f"((d)[0]), "+f"((d)[1]), "+f"((d)[2]), "+f"((d)[3]) \
  : "r"((a)[0]),"r"((a)[1]),"r"((a)[2]),"r"((a)[3]), "r"((b)[0]),"r"((b)[1]))
#define CP_ASYNC16(dst, src) asm volatile("cp.async.cg.shared.global [%0], [%1], 16;" :: "r"(dst), "l"(src))
#define CP_COMMIT() asm volatile("cp.async.commit_group;" ::: "memory")
#define CP_WAIT0()  asm volatile("cp.async.wait_group 0;" ::: "memory")
#define CP_WAIT1()  asm volatile("cp.async.wait_group 1;" ::: "memory")

__device__ __forceinline__ float ex2f(float x) {
    float y; asm("ex2.approx.ftz.f32 %0, %1;" : "=f"(y) : "f"(x)); return y;
}
__device__ __forceinline__ uint32_t pack_h2(float a, float b) {
    uint32_t u;
    asm("{ .reg .f16 lo, hi; cvt.rn.f16.f32 lo, %1; cvt.rn.f16.f32 hi, %2; mov.b32 %0, {lo, hi}; }"
        : "=r"(u) : "f"(a), "f"(b));
    return u;
}

// ---------------------------------------------------------------------------
// fp32 -> fp16 convert (row-major, 8 elems per thread)
// ---------------------------------------------------------------------------
__global__ __launch_bounds__(256) void conv16(const float* __restrict__ src,
                                              __half* __restrict__ dst)
{
    int idx = blockIdx.x * 256 + threadIdx.x;
    const float4* s = (const float4*)src + (size_t)idx * 2;
    float4 a0 = s[0], a1 = s[1];
    uint32_t o[4];
    o[0] = pack_h2(a0.x, a0.y);
    o[1] = pack_h2(a0.z, a0.w);
    o[2] = pack_h2(a1.x, a1.y);
    o[3] = pack_h2(a1.z, a1.w);
    ((uint4*)dst)[idx] = *(uint4*)o;
}

// transpose + convert: out[d][o] = W[o][d]
__global__ void convT16(const float* __restrict__ W, __half* __restrict__ dst)
{
    __shared__ float t[32][33];
    int bx = blockIdx.x * 32, by = blockIdx.y * 32;
    int tx = threadIdx.x, ty = threadIdx.y;
    #pragma unroll
    for (int i = 0; i < 4; i++)
        t[ty + 8*i][tx] = W[(size_t)(by + ty + 8*i) * DD + bx + tx];
    __syncthreads();
    #pragma unroll
    for (int i = 0; i < 4; i++) {
        float v = t[tx][ty + 8*i];
        dst[(size_t)(bx + ty + 8*i) * DD + by + tx] = __float2half_rn(v);
    }
}

// ---------------------------------------------------------------------------
// fp16 HMMA GEMM: C[m,o] = sum_d A[m,d]*B[o,d], 1-term fp16, fp32 accum.
// CTA 128x128, 8 warps (32x64 warp tiles), BK=32, double-buffered cp.async.
// scatter=1: write fp16 scattered to [b,n,p,h] (QKV path, Q pre-scaled)
// scatter=0: write fp32 row-major (O-projection)
// ---------------------------------------------------------------------------
#define ROWB 80                  // 32 fp16 (64B) + 16B pad
#define MATB (128*ROWB)          // 10240
#define STAGEB (2*MATB)          // 20480: A, B

__global__ __launch_bounds__(256, 2) void gemm_f16(
    const __half* __restrict__ A16,
    const __half* __restrict__ B0, const __half* __restrict__ B1,
    const __half* __restrict__ B2,
    float* __restrict__ of,
    __half* __restrict__ q16, __half* __restrict__ k16, __half* __restrict__ v16,
    int scatter)
{
    extern __shared__ char smem[];
    const int tid = threadIdx.x, lane = tid & 31, wid = tid >> 5;
    const int wm = wid & 3, wn = wid >> 2;
    const int n0 = blockIdx.x * 128, m0 = blockIdx.y * 128, z = blockIdx.z;
    const __half* Bt = (z == 0) ? B0 : (z == 1) ? B1 : B2;
    __half* out16 = (z == 0) ? q16 : (z == 1) ? k16 : v16;
    const float scalef = (scatter && z == 0) ? QSCALE : 1.0f;

    const __half* gsrc[2] = { A16 + (size_t)m0 * DD, Bt + (size_t)n0 * DD };

    const uint32_t sbase = smem_u32(smem);
    const int lrow = tid >> 2;       // 0..63
    const int lseg = tid & 3;        // 16B segment of 64B row
    const int g = lane >> 3, rl = lane & 7;

    float acc[2][8][4];
    #pragma unroll
    for (int t = 0; t < 2; t++)
        #pragma unroll
        for (int j = 0; j < 8; j++)
            #pragma unroll
            for (int x = 0; x < 4; x++) acc[t][j][x] = 0.f;

    {
        #pragma unroll
        for (int i = 0; i < 4; i++) {
            int mat = i >> 1;
            int r = ((i & 1) << 6) | lrow;
            CP_ASYNC16(sbase + mat * MATB + r * ROWB + lseg * 16,
                       gsrc[mat] + (size_t)r * DD + lseg * 8);
        }
        CP_COMMIT();
    }

    for (int it = 0; it < 32; it++) {
        CP_WAIT0();
        __syncthreads();
        if (it + 1 < 32) {
            int k0 = (it + 1) * 32;
            uint32_t sb = sbase + ((it + 1) & 1) * STAGEB;
            #pragma unroll
            for (int i = 0; i < 4; i++) {
                int mat = i >> 1;
                int r = ((i & 1) << 6) | lrow;
                CP_ASYNC16(sb + mat * MATB + r * ROWB + lseg * 16,
                           gsrc[mat] + (size_t)r * DD + k0 + lseg * 8);
            }
            CP_COMMIT();
        }

        const uint32_t st = sbase + (it & 1) * STAGEB;
        #pragma unroll
        for (int kh = 0; kh < 2; kh++) {
            uint32_t af[2][4], bf[4][4];
            #pragma unroll
            for (int t = 0; t < 2; t++) {
                int row = wm * 32 + t * 16 + (lane & 15);
                LDSM_X4(af[t], st + row * ROWB + (lane >> 4) * 16 + kh * 32);
            }
            #pragma unroll
            for (int jp = 0; jp < 4; jp++) {
                int row = wn * 64 + (2 * jp + (g >> 1)) * 8 + rl;
                LDSM_X4(bf[jp], st + MATB + row * ROWB + (g & 1) * 16 + kh * 32);
            }
            #pragma unroll
            for (int t = 0; t < 2; t++)
                #pragma unroll
                for (int jp = 0; jp < 4; jp++) {
                    MMA_F16(acc[t][2*jp],   af[t], bf[jp]);
                    MMA_F16(acc[t][2*jp+1], af[t], bf[jp]+2);
                }
        }
        __syncthreads();
    }

    // epilogue
    const int r0 = lane >> 2, c0 = (lane & 3) * 2;
    #pragma unroll
    for (int t = 0; t < 2; t++) {
        #pragma unroll
        for (int j = 0; j < 8; j++) {
            int o = n0 + wn * 64 + j * 8 + c0;
            #pragma unroll
            for (int h2 = 0; h2 < 2; h2++) {
                int m = m0 + wm * 32 + t * 16 + r0 + h2 * 8;
                float x0 = acc[t][j][2*h2] * scalef, x1 = acc[t][j][2*h2+1] * scalef;
                if (scatter) {
                    int b = m >> 11, p = m & 2047;
                    int n = o >> 6, hh = o & 63;
                    size_t didx = ((size_t)(b * NH + n) * SS + p) * HD + hh;
                    *(uint32_t*)(out16 + didx) = pack_h2(x0, x1);
                } else {
                    *(float2*)(of + (size_t)m * DD + o) = make_float2(x0, x1);
                }
            }
        }
    }
}

// ---------------------------------------------------------------------------
// Tensor-core flash attention (causal), 1-term fp16, exp2-domain softmax.
// CTA: 128 q-rows, 8 warps x 16 rows. K-tiles of 64, double-buffered.
// Writes fp16 output in [b,p,(n,h)] layout for the O-projection GEMM.
// ---------------------------------------------------------------------------
#define AROWB 144               // 64 fp16 (128B) + 16B pad
#define AMAT  (64*AROWB)        // 9216
#define ASTG  (2*AMAT)          // 18432: K, V
#define AQB   (128*AROWB)       // 18432

__global__ __launch_bounds__(256, 1) void attn_mma(
    const __half* __restrict__ Qg, const __half* __restrict__ Kg,
    const __half* __restrict__ Vg,
    __half* __restrict__ Og)
{
    extern __shared__ char smem[];
    const uint32_t sb = smem_u32(smem);
    const int tid = threadIdx.x, lane = tid & 31, wid = tid >> 5;
    const int qb = (int)gridDim.x - 1 - (int)blockIdx.x;   // long CTAs first
    const int q0 = qb * 128;
    const int n = blockIdx.y, b = blockIdx.z;
    const size_t base = (size_t)(b * NH + n) * SS * HD;
    const int nt = 2 * qb + 2;
    const uint32_t ST0 = sb + AQB;

    auto load_tile = [&](int t) {
        uint32_t stb = ST0 + (uint32_t)(t & 1) * ASTG;
        int key0 = t * 64;
        const __half* ms[2] = { Kg + base + (size_t)key0 * HD, Vg + base + (size_t)key0 * HD };
        #pragma unroll
        for (int mt = 0; mt < 2; mt++) {
            #pragma unroll
            for (int u = 0; u < 2; u++) {
                int idx = tid + u * 256;     // 0..511
                int row = idx >> 3, seg = idx & 7;
                CP_ASYNC16(stb + mt * AMAT + row * AROWB + seg * 16,
                           ms[mt] + (size_t)row * HD + seg * 8);
            }
        }
    };

    // Q load (grouped with tile 0)
    {
        const __half* qs = Qg + base + (size_t)q0 * HD;
        #pragma unroll
        for (int u = 0; u < 4; u++) {
            int idx = tid + u * 256;         // 0..1023
            int row = idx >> 3, seg = idx & 7;
            CP_ASYNC16(sb + row * AROWB + seg * 16, qs + (size_t)row * HD + seg * 8);
        }
        load_tile(0);
        CP_COMMIT();
        load_tile(1);
        CP_COMMIT();
    }

    CP_WAIT1();
    __syncthreads();

    // Q fragments (registers, persist)
    uint32_t qf[4][4];
    const int qw = wid * 16;
    #pragma unroll
    for (int kh = 0; kh < 4; kh++) {
        uint32_t a = sb + (qw + (lane & 15)) * AROWB + kh * 32 + (lane >> 4) * 16;
        LDSM_X4(qf[kh], a);
    }

    float m0r = -1e30f, m1r = -1e30f, l0r = 0.f, l1r = 0.f;
    float O[8][4];
    #pragma unroll
    for (int j = 0; j < 8; j++)
        #pragma unroll
        for (int x = 0; x < 4; x++) O[j][x] = 0.f;

    const int row0 = q0 + qw + (lane >> 2);
    const int cl = (lane & 3) * 2;

    for (int it = 0; it < nt; it++) {
        const uint32_t stb = ST0 + (uint32_t)(it & 1) * ASTG;

        // ---- S = Q K^T (1-term fp16)
        float S[8][4];
        #pragma unroll
        for (int j = 0; j < 8; j++)
            #pragma unroll
            for (int x = 0; x < 4; x++) S[j][x] = 0.f;

        #pragma unroll
        for (int kh = 0; kh < 4; kh++) {
            uint32_t kb[4][4];
            const int g = lane >> 3, r = lane & 7;
            #pragma unroll
            for (int jp = 0; jp < 4; jp++) {
                uint32_t a = stb + (uint32_t)(((jp * 2 + (g >> 1)) * 8 + r) * AROWB + (g & 1) * 16 + kh * 32);
                LDSM_X4(kb[jp], a);
            }
            #pragma unroll
            for (int jp = 0; jp < 4; jp++) {
                MMA_F16(S[2*jp],   qf[kh], kb[jp]);
                MMA_F16(S[2*jp+1], qf[kh], kb[jp]+2);
            }
        }

        // ---- causal mask (near diagonal only)
        if (it >= nt - 2) {
            const int kbase = it * 64 + cl;
            #pragma unroll
            for (int j = 0; j < 8; j++) {
                int c = kbase + j * 8;
                if (c     > row0)     S[j][0] = -1e30f;
                if (c + 1 > row0)     S[j][1] = -1e30f;
                if (c     > row0 + 8) S[j][2] = -1e30f;
                if (c + 1 > row0 + 8) S[j][3] = -1e30f;
            }
        }

        // ---- online softmax (log2 domain)
        float mn0 = m0r, mn1 = m1r;
        #pragma unroll
        for (int j = 0; j < 8; j++) {
            mn0 = fmaxf(mn0, fmaxf(S[j][0], S[j][1]));
            mn1 = fmaxf(mn1, fmaxf(S[j][2], S[j][3]));
        }
        mn0 = fmaxf(mn0, __shfl_xor_sync(0xffffffffu, mn0, 1));
        mn0 = fmaxf(mn0, __shfl_xor_sync(0xffffffffu, mn0, 2));
        mn1 = fmaxf(mn1, __shfl_xor_sync(0xffffffffu, mn1, 1));
        mn1 = fmaxf(mn1, __shfl_xor_sync(0xffffffffu, mn1, 2));

        float c0 = ex2f(m0r - mn0), c1 = ex2f(m1r - mn1);
        l0r *= c0; l1r *= c1;
        #pragma unroll
        for (int j = 0; j < 8; j++) {
            O[j][0] *= c0; O[j][1] *= c0; O[j][2] *= c1; O[j][3] *= c1;
        }
        m0r = mn0; m1r = mn1;

        uint32_t ph[4][4];
        float s0 = 0.f, s1 = 0.f;
        #pragma unroll
        for (int j = 0; j < 8; j++) {
            float p0 = ex2f(S[j][0] - mn0), p1 = ex2f(S[j][1] - mn0);
            float p2 = ex2f(S[j][2] - mn1), p3 = ex2f(S[j][3] - mn1);
            s0 += p0 + p1; s1 += p2 + p3;
            int kk = j >> 1, i0 = (j & 1) * 2;
            ph[kk][i0]   = pack_h2(p0, p1);
            ph[kk][i0+1] = pack_h2(p2, p3);
        }
        s0 += __shfl_xor_sync(0xffffffffu, s0, 1);
        s0 += __shfl_xor_sync(0xffffffffu, s0, 2);
        s1 += __shfl_xor_sync(0xffffffffu, s1, 1);
        s1 += __shfl_xor_sync(0xffffffffu, s1, 2);
        l0r += s0; l1r += s1;

        // ---- O += P V (1-term fp16)
        {
            const int g = lane >> 3, r = lane & 7;
            #pragma unroll
            for (int kk = 0; kk < 4; kk++) {
                #pragma unroll
                for (int jn = 0; jn < 4; jn++) {
                    uint32_t vb[4];
                    uint32_t a = stb + AMAT
                        + (uint32_t)((kk * 16 + ((g & 1) << 3) + r) * AROWB + (2 * jn + (g >> 1)) * 16);
                    LDSM_X4T(vb, a);
                    MMA_F16(O[2*jn],   ph[kk], vb);
                    MMA_F16(O[2*jn+1], ph[kk], vb+2);
                }
            }
        }

        __syncthreads();
        int nx = it + 2;
        if (nx < nt) { load_tile(nx); CP_COMMIT(); }
        if (it + 1 < nt) {
            if (nx < nt) CP_WAIT1(); else CP_WAIT0();
            __syncthreads();
        }
    }

    // ---- write fp16 output: rows (b, q), cols n*64 + hd
    float inv0 = 1.f / l0r, inv1 = 1.f / l1r;
    size_t orow0 = ((size_t)(b * SS + row0)) * DD + n * HD;
    size_t orow1 = orow0 + (size_t)8 * DD;
    #pragma unroll
    for (int nb = 0; nb < 8; nb++) {
        int d = nb * 8 + cl;
        *(uint32_t*)(Og + orow0 + d) = pack_h2(O[nb][0] * inv0, O[nb][1] * inv0);
        *(uint32_t*)(Og + orow1 + d) = pack_h2(O[nb][2] * inv1, O[nb][3] * inv1);
    }
}

// ---------------------------------------------------------------------------
extern "C" void kernel_launch(void* const* d_in, const int* in_sizes, int n_in,
                              void* d_out, int out_size)
{
    const float* residual = (const float*)d_in[0];
    const float* W_Q = (const float*)d_in[1];
    const float* W_K = (const float*)d_in[2];
    const float* W_V = (const float*)d_in[3];
    const float* W_O = (const float*)d_in[4];
    float* out = (float*)d_out;

    __half *a16, *a216, *wq, *wk, *wv, *wo, *q16, *k16, *v16;
    cudaGetSymbolAddress((void**)&a16,  g_A16);
    cudaGetSymbolAddress((void**)&a216, g_A216);
    cudaGetSymbolAddress((void**)&wq,   g_WQ16);
    cudaGetSymbolAddress((void**)&wk,   g_WK16);
    cudaGetSymbolAddress((void**)&wv,   g_WV16);
    cudaGetSymbolAddress((void**)&wo,   g_WO16);
    cudaGetSymbolAddress((void**)&q16,  g_Q16);
    cudaGetSymbolAddress((void**)&k16,  g_K16);
    cudaGetSymbolAddress((void**)&v16,  g_V16);

    const int GSMEM = 2 * STAGEB;              // 40960
    const int ASMEM = AQB + 2 * ASTG;          // 55296
    cudaFuncSetAttribute(gemm_f16, cudaFuncAttributeMaxDynamicSharedMemorySize, GSMEM);
    cudaFuncSetAttribute(attn_mma, cudaFuncAttributeMaxDynamicSharedMemorySize, ASMEM);

    conv16<<<MM*DD/8/256, 256>>>(residual, a16);
    conv16<<<DD*DD/8/256, 256>>>(W_Q, wq);
    conv16<<<DD*DD/8/256, 256>>>(W_K, wk);
    conv16<<<DD*DD/8/256, 256>>>(W_V, wv);
    convT16<<<dim3(32,32), dim3(32,8)>>>(W_O, wo);

    // QKV projections -> fp16, scattered [b,n,p,h]; Q pre-scaled
    gemm_f16<<<dim3(8, 32, 3), 256, GSMEM>>>(a16, wq, wk, wv,
        nullptr, q16, k16, v16, 1);

    // 1-term fp16 flash attention -> fp16 [b,p,(n,h)]
    attn_mma<<<dim3(SS/128, NH, BB), 256, ASMEM>>>(q16, k16, v16, a216);

    // output projection (fp32 out)
    gemm_f16<<<dim3(8, 32, 1), 256, GSMEM>>>(a216, wo, wo, wo,
        out, nullptr, nullptr, nullptr, 0);
}

// round 9
// speedup vs baseline: 4.8840x; 1.0337x over previous
#include <cuda_runtime.h>
#include <cuda_bf16.h>
#include <cuda_fp16.h>
#include <cstdint>
#include <math.h>

// Problem constants
#define BB 2
#define SS 2048
#define DD 1024
#define NH 16
#define HD 64
#define MM (BB*SS)      // 4096
#define QSCALE 0.18033688011112042f   // 0.125 * log2(e)

// ---------------------------------------------------------------------------
// Scratch (device globals)
// ---------------------------------------------------------------------------
__device__ __align__(16) __half g_A16[MM*DD];       // residual fp16
__device__ __align__(16) __half g_A216[MM*DD];      // attn out fp16
__device__ __align__(16) __half g_WQ16[DD*DD];      // pre-scaled by QSCALE
__device__ __align__(16) __half g_WK16[DD*DD];
__device__ __align__(16) __half g_WV16[DD*DD];
__device__ __align__(16) __half g_WO16[DD*DD];      // transposed W_O
__device__ __align__(16) __half g_Q16[BB*NH*SS*HD];
__device__ __align__(16) __half g_K16[BB*NH*SS*HD];
__device__ __align__(16) __half g_V16[BB*NH*SS*HD];

// ---------------------------------------------------------------------------
// helpers
// ---------------------------------------------------------------------------
__device__ __forceinline__ uint32_t smem_u32(const void* p) {
    uint32_t a;
    asm("{ .reg .u64 t; cvta.to.shared.u64 t, %1; cvt.u32.u64 %0, t; }" : "=r"(a) : "l"(p));
    return a;
}
#define LDSM_X4(r, a) asm volatile("ldmatrix.sync.aligned.m8n8.x4.shared.b16 {%0,%1,%2,%3}, [%4];" \
  : "=r"((r)[0]),"=r"((r)[1]),"=r"((r)[2]),"=r"((r)[3]) : "r"(a))
#define LDSM_X4T(r, a) asm volatile("ldmatrix.sync.aligned.m8n8.x4.trans.shared.b16 {%0,%1,%2,%3}, [%4];" \
  : "=r"((r)[0]),"=r"((r)[1]),"=r"((r)[2]),"=r"((r)[3]) : "r"(a))
#define MMA_F16(d, a, b) asm volatile( \
  "mma.sync.aligned.m16n8k16.row.col.f32.f16.f16.f32 {%0,%1,%2,%3},{%4,%5,%6,%7},{%8,%9},{%0,%1,%2,%3};" \
  : "+f"((d)[0]), "+f"((d)[1]), "+f"((d)[2]), "+f"((d)[3]) \
  : "r"((a)[0]),"r"((a)[1]),"r"((a)[2]),"r"((a)[3]), "r"((b)[0]),"r"((b)[1]))
#define CP_ASYNC16(dst, src) asm volatile("cp.async.cg.shared.global [%0], [%1], 16;" :: "r"(dst), "l"(src))
#define CP_COMMIT() asm volatile("cp.async.commit_group;" ::: "memory")
#define CP_WAIT0()  asm volatile("cp.async.wait_group 0;" ::: "memory")
#define CP_WAIT1()  asm volatile("cp.async.wait_group 1;" ::: "memory")

__device__ __forceinline__ float ex2f(float x) {
    float y; asm("ex2.approx.ftz.f32 %0, %1;" : "=f"(y) : "f"(x)); return y;
}
__device__ __forceinline__ uint32_t pack_h2(float a, float b) {
    uint32_t u;
    asm("{ .reg .f16 lo, hi; cvt.rn.f16.f32 lo, %1; cvt.rn.f16.f32 hi, %2; mov.b32 %0, {lo, hi}; }"
        : "=r"(u) : "f"(a), "f"(b));
    return u;
}

// ---------------------------------------------------------------------------
// Fused prep: one launch converts everything.
// blocks [0, 2048)              : residual -> g_A16          (8 elems/thread)
// blocks [2048, 2560)           : W_Q * QSCALE -> g_WQ16
// blocks [2560, 3072)           : W_K -> g_WK16
// blocks [3072, 3584)           : W_V -> g_WV16
// blocks [3584, 4608)           : W_O transpose -> g_WO16    (32x32 tiles)
// ---------------------------------------------------------------------------
__global__ __launch_bounds__(256) void prep_all(
    const float* __restrict__ residual, const float* __restrict__ W_Q,
    const float* __restrict__ W_K, const float* __restrict__ W_V,
    const float* __restrict__ W_O)
{
    int blk = blockIdx.x;
    if (blk < 3584) {
        const float* src;
        __half* dst;
        float sc = 1.0f;
        int base;
        if (blk < 2048)      { src = residual; dst = g_A16;  base = blk; }
        else if (blk < 2560) { src = W_Q; dst = g_WQ16; base = blk - 2048; sc = QSCALE; }
        else if (blk < 3072) { src = W_K; dst = g_WK16; base = blk - 2560; }
        else                 { src = W_V; dst = g_WV16; base = blk - 3072; }
        int idx = base * 256 + threadIdx.x;
        const float4* s = (const float4*)src + (size_t)idx * 2;
        float4 a0 = s[0], a1 = s[1];
        uint32_t o[4];
        o[0] = pack_h2(a0.x * sc, a0.y * sc);
        o[1] = pack_h2(a0.z * sc, a0.w * sc);
        o[2] = pack_h2(a1.x * sc, a1.y * sc);
        o[3] = pack_h2(a1.z * sc, a1.w * sc);
        ((uint4*)dst)[idx] = *(uint4*)o;
    } else {
        // W_O transpose: out[d][o] = W_O[o][d]
        __shared__ float t[32][33];
        int tile = blk - 3584;                 // 0..1023
        int bx = (tile & 31) * 32;             // d tile
        int by = (tile >> 5) * 32;             // o tile
        int tx = threadIdx.x & 31, ty = threadIdx.x >> 5;
        #pragma unroll
        for (int i = 0; i < 4; i++)
            t[ty + 8*i][tx] = W_O[(size_t)(by + ty + 8*i) * DD + bx + tx];
        __syncthreads();
        #pragma unroll
        for (int i = 0; i < 4; i++) {
            float v = t[tx][ty + 8*i];
            g_WO16[(size_t)(bx + ty + 8*i) * DD + by + tx] = __float2half_rn(v);
        }
    }
}

// ---------------------------------------------------------------------------
// fp16 HMMA GEMM: C[m,o] = sum_d A[m,d]*B[o,d], 1-term fp16, fp32 accum.
// CTA 128x128, 8 warps (32x64 warp tiles), BK=32, double-buffered cp.async.
// scatter=1: write fp16 scattered to [b,n,p,h] (QKV path)
// scatter=0: write fp32 row-major (O-projection)
// ---------------------------------------------------------------------------
#define ROWB 80                  // 32 fp16 (64B) + 16B pad
#define MATB (128*ROWB)          // 10240
#define STAGEB (2*MATB)          // 20480: A, B

__global__ __launch_bounds__(256, 2) void gemm_f16(
    const __half* __restrict__ A16,
    const __half* __restrict__ B0, const __half* __restrict__ B1,
    const __half* __restrict__ B2,
    float* __restrict__ of,
    __half* __restrict__ q16, __half* __restrict__ k16, __half* __restrict__ v16,
    int scatter)
{
    extern __shared__ char smem[];
    const int tid = threadIdx.x, lane = tid & 31, wid = tid >> 5;
    const int wm = wid & 3, wn = wid >> 2;
    const int n0 = blockIdx.x * 128, m0 = blockIdx.y * 128, z = blockIdx.z;
    const __half* Bt = (z == 0) ? B0 : (z == 1) ? B1 : B2;
    __half* out16 = (z == 0) ? q16 : (z == 1) ? k16 : v16;

    const __half* gsrc[2] = { A16 + (size_t)m0 * DD, Bt + (size_t)n0 * DD };

    const uint32_t sbase = smem_u32(smem);
    const int lrow = tid >> 2;       // 0..63
    const int lseg = tid & 3;        // 16B segment of 64B row
    const int g = lane >> 3, rl = lane & 7;

    float acc[2][8][4];
    #pragma unroll
    for (int t = 0; t < 2; t++)
        #pragma unroll
        for (int j = 0; j < 8; j++)
            #pragma unroll
            for (int x = 0; x < 4; x++) acc[t][j][x] = 0.f;

    {
        #pragma unroll
        for (int i = 0; i < 4; i++) {
            int mat = i >> 1;
            int r = ((i & 1) << 6) | lrow;
            CP_ASYNC16(sbase + mat * MATB + r * ROWB + lseg * 16,
                       gsrc[mat] + (size_t)r * DD + lseg * 8);
        }
        CP_COMMIT();
    }

    for (int it = 0; it < 32; it++) {
        CP_WAIT0();
        __syncthreads();
        if (it + 1 < 32) {
            int k0 = (it + 1) * 32;
            uint32_t sb = sbase + ((it + 1) & 1) * STAGEB;
            #pragma unroll
            for (int i = 0; i < 4; i++) {
                int mat = i >> 1;
                int r = ((i & 1) << 6) | lrow;
                CP_ASYNC16(sb + mat * MATB + r * ROWB + lseg * 16,
                           gsrc[mat] + (size_t)r * DD + k0 + lseg * 8);
            }
            CP_COMMIT();
        }

        const uint32_t st = sbase + (it & 1) * STAGEB;
        #pragma unroll
        for (int kh = 0; kh < 2; kh++) {
            uint32_t af[2][4], bf[4][4];
            #pragma unroll
            for (int t = 0; t < 2; t++) {
                int row = wm * 32 + t * 16 + (lane & 15);
                LDSM_X4(af[t], st + row * ROWB + (lane >> 4) * 16 + kh * 32);
            }
            #pragma unroll
            for (int jp = 0; jp < 4; jp++) {
                int row = wn * 64 + (2 * jp + (g >> 1)) * 8 + rl;
                LDSM_X4(bf[jp], st + MATB + row * ROWB + (g & 1) * 16 + kh * 32);
            }
            #pragma unroll
            for (int t = 0; t < 2; t++)
                #pragma unroll
                for (int jp = 0; jp < 4; jp++) {
                    MMA_F16(acc[t][2*jp],   af[t], bf[jp]);
                    MMA_F16(acc[t][2*jp+1], af[t], bf[jp]+2);
                }
        }
        __syncthreads();
    }

    // epilogue
    const int r0 = lane >> 2, c0 = (lane & 3) * 2;
    #pragma unroll
    for (int t = 0; t < 2; t++) {
        #pragma unroll
        for (int j = 0; j < 8; j++) {
            int o = n0 + wn * 64 + j * 8 + c0;
            #pragma unroll
            for (int h2 = 0; h2 < 2; h2++) {
                int m = m0 + wm * 32 + t * 16 + r0 + h2 * 8;
                float x0 = acc[t][j][2*h2], x1 = acc[t][j][2*h2+1];
                if (scatter) {
                    int b = m >> 11, p = m & 2047;
                    int n = o >> 6, hh = o & 63;
                    size_t didx = ((size_t)(b * NH + n) * SS + p) * HD + hh;
                    *(uint32_t*)(out16 + didx) = pack_h2(x0, x1);
                } else {
                    *(float2*)(of + (size_t)m * DD + o) = make_float2(x0, x1);
                }
            }
        }
    }
}

// ---------------------------------------------------------------------------
// Tensor-core flash attention (causal), 1-term fp16, exp2-domain softmax.
// CTA: 128 q-rows, 8 warps x 16 rows. K-tiles of 64, double-buffered.
// Writes fp16 output in [b,p,(n,h)] layout for the O-projection GEMM.
// ---------------------------------------------------------------------------
#define AROWB 144               // 64 fp16 (128B) + 16B pad
#define AMAT  (64*AROWB)        // 9216
#define ASTG  (2*AMAT)          // 18432: K, V
#define AQB   (128*AROWB)       // 18432

__global__ __launch_bounds__(256, 1) void attn_mma(
    const __half* __restrict__ Qg, const __half* __restrict__ Kg,
    const __half* __restrict__ Vg,
    __half* __restrict__ Og)
{
    extern __shared__ char smem[];
    const uint32_t sb = smem_u32(smem);
    const int tid = threadIdx.x, lane = tid & 31, wid = tid >> 5;
    const int qb = (int)gridDim.x - 1 - (int)blockIdx.x;   // long CTAs first
    const int q0 = qb * 128;
    const int n = blockIdx.y, b = blockIdx.z;
    const size_t base = (size_t)(b * NH + n) * SS * HD;
    const int nt = 2 * qb + 2;
    const uint32_t ST0 = sb + AQB;

    auto load_tile = [&](int t) {
        uint32_t stb = ST0 + (uint32_t)(t & 1) * ASTG;
        int key0 = t * 64;
        const __half* ms[2] = { Kg + base + (size_t)key0 * HD, Vg + base + (size_t)key0 * HD };
        #pragma unroll
        for (int mt = 0; mt < 2; mt++) {
            #pragma unroll
            for (int u = 0; u < 2; u++) {
                int idx = tid + u * 256;     // 0..511
                int row = idx >> 3, seg = idx & 7;
                CP_ASYNC16(stb + mt * AMAT + row * AROWB + seg * 16,
                           ms[mt] + (size_t)row * HD + seg * 8);
            }
        }
    };

    // Q load (grouped with tile 0)
    {
        const __half* qs = Qg + base + (size_t)q0 * HD;
        #pragma unroll
        for (int u = 0; u < 4; u++) {
            int idx = tid + u * 256;         // 0..1023
            int row = idx >> 3, seg = idx & 7;
            CP_ASYNC16(sb + row * AROWB + seg * 16, qs + (size_t)row * HD + seg * 8);
        }
        load_tile(0);
        CP_COMMIT();
        load_tile(1);
        CP_COMMIT();
    }

    CP_WAIT1();
    __syncthreads();

    // Q fragments (registers, persist)
    uint32_t qf[4][4];
    const int qw = wid * 16;
    #pragma unroll
    for (int kh = 0; kh < 4; kh++) {
        uint32_t a = sb + (qw + (lane & 15)) * AROWB + kh * 32 + (lane >> 4) * 16;
        LDSM_X4(qf[kh], a);
    }

    float m0r = -1e30f, m1r = -1e30f, l0r = 0.f, l1r = 0.f;
    float O[8][4];
    #pragma unroll
    for (int j = 0; j < 8; j++)
        #pragma unroll
        for (int x = 0; x < 4; x++) O[j][x] = 0.f;

    const int row0 = q0 + qw + (lane >> 2);
    const int cl = (lane & 3) * 2;

    for (int it = 0; it < nt; it++) {
        const uint32_t stb = ST0 + (uint32_t)(it & 1) * ASTG;

        // ---- S = Q K^T (1-term fp16)
        float S[8][4];
        #pragma unroll
        for (int j = 0; j < 8; j++)
            #pragma unroll
            for (int x = 0; x < 4; x++) S[j][x] = 0.f;

        #pragma unroll
        for (int kh = 0; kh < 4; kh++) {
            uint32_t kb[4][4];
            const int g = lane >> 3, r = lane & 7;
            #pragma unroll
            for (int jp = 0; jp < 4; jp++) {
                uint32_t a = stb + (uint32_t)(((jp * 2 + (g >> 1)) * 8 + r) * AROWB + (g & 1) * 16 + kh * 32);
                LDSM_X4(kb[jp], a);
            }
            #pragma unroll
            for (int jp = 0; jp < 4; jp++) {
                MMA_F16(S[2*jp],   qf[kh], kb[jp]);
                MMA_F16(S[2*jp+1], qf[kh], kb[jp]+2);
            }
        }

        // ---- causal mask (near diagonal only)
        if (it >= nt - 2) {
            const int kbase = it * 64 + cl;
            #pragma unroll
            for (int j = 0; j < 8; j++) {
                int c = kbase + j * 8;
                if (c     > row0)     S[j][0] = -1e30f;
                if (c + 1 > row0)     S[j][1] = -1e30f;
                if (c     > row0 + 8) S[j][2] = -1e30f;
                if (c + 1 > row0 + 8) S[j][3] = -1e30f;
            }
        }

        // ---- online softmax (log2 domain)
        float mn0 = m0r, mn1 = m1r;
        #pragma unroll
        for (int j = 0; j < 8; j++) {
            mn0 = fmaxf(mn0, fmaxf(S[j][0], S[j][1]));
            mn1 = fmaxf(mn1, fmaxf(S[j][2], S[j][3]));
        }
        mn0 = fmaxf(mn0, __shfl_xor_sync(0xffffffffu, mn0, 1));
        mn0 = fmaxf(mn0, __shfl_xor_sync(0xffffffffu, mn0, 2));
        mn1 = fmaxf(mn1, __shfl_xor_sync(0xffffffffu, mn1, 1));
        mn1 = fmaxf(mn1, __shfl_xor_sync(0xffffffffu, mn1, 2));

        float c0 = ex2f(m0r - mn0), c1 = ex2f(m1r - mn1);
        l0r *= c0; l1r *= c1;
        #pragma unroll
        for (int j = 0; j < 8; j++) {
            O[j][0] *= c0; O[j][1] *= c0; O[j][2] *= c1; O[j][3] *= c1;
        }
        m0r = mn0; m1r = mn1;

        uint32_t ph[4][4];
        float s0 = 0.f, s1 = 0.f;
        #pragma unroll
        for (int j = 0; j < 8; j++) {
            float p0 = ex2f(S[j][0] - mn0), p1 = ex2f(S[j][1] - mn0);
            float p2 = ex2f(S[j][2] - mn1), p3 = ex2f(S[j][3] - mn1);
            s0 += p0 + p1; s1 += p2 + p3;
            int kk = j >> 1, i0 = (j & 1) * 2;
            ph[kk][i0]   = pack_h2(p0, p1);
            ph[kk][i0+1] = pack_h2(p2, p3);
        }
        s0 += __shfl_xor_sync(0xffffffffu, s0, 1);
        s0 += __shfl_xor_sync(0xffffffffu, s0, 2);
        s1 += __shfl_xor_sync(0xffffffffu, s1, 1);
        s1 += __shfl_xor_sync(0xffffffffu, s1, 2);
        l0r += s0; l1r += s1;

        // ---- O += P V (1-term fp16)
        {
            const int g = lane >> 3, r = lane & 7;
            #pragma unroll
            for (int kk = 0; kk < 4; kk++) {
                #pragma unroll
                for (int jn = 0; jn < 4; jn++) {
                    uint32_t vb[4];
                    uint32_t a = stb + AMAT
                        + (uint32_t)((kk * 16 + ((g & 1) << 3) + r) * AROWB + (2 * jn + (g >> 1)) * 16);
                    LDSM_X4T(vb, a);
                    MMA_F16(O[2*jn],   ph[kk], vb);
                    MMA_F16(O[2*jn+1], ph[kk], vb+2);
                }
            }
        }

        __syncthreads();
        int nx = it + 2;
        if (nx < nt) { load_tile(nx); CP_COMMIT(); }
        if (it + 1 < nt) {
            if (nx < nt) CP_WAIT1(); else CP_WAIT0();
            __syncthreads();
        }
    }

    // ---- write fp16 output: rows (b, q), cols n*64 + hd
    float inv0 = 1.f / l0r, inv1 = 1.f / l1r;
    size_t orow0 = ((size_t)(b * SS + row0)) * DD + n * HD;
    size_t orow1 = orow0 + (size_t)8 * DD;
    #pragma unroll
    for (int nb = 0; nb < 8; nb++) {
        int d = nb * 8 + cl;
        *(uint32_t*)(Og + orow0 + d) = pack_h2(O[nb][0] * inv0, O[nb][1] * inv0);
        *(uint32_t*)(Og + orow1 + d) = pack_h2(O[nb][2] * inv1, O[nb][3] * inv1);
    }
}

// ---------------------------------------------------------------------------
extern "C" void kernel_launch(void* const* d_in, const int* in_sizes, int n_in,
                              void* d_out, int out_size)
{
    const float* residual = (const float*)d_in[0];
    const float* W_Q = (const float*)d_in[1];
    const float* W_K = (const float*)d_in[2];
    const float* W_V = (const float*)d_in[3];
    const float* W_O = (const float*)d_in[4];
    float* out = (float*)d_out;

    __half *a16, *a216, *wq, *wk, *wv, *wo, *q16, *k16, *v16;
    cudaGetSymbolAddress((void**)&a16,  g_A16);
    cudaGetSymbolAddress((void**)&a216, g_A216);
    cudaGetSymbolAddress((void**)&wq,   g_WQ16);
    cudaGetSymbolAddress((void**)&wk,   g_WK16);
    cudaGetSymbolAddress((void**)&wv,   g_WV16);
    cudaGetSymbolAddress((void**)&wo,   g_WO16);
    cudaGetSymbolAddress((void**)&q16,  g_Q16);
    cudaGetSymbolAddress((void**)&k16,  g_K16);
    cudaGetSymbolAddress((void**)&v16,  g_V16);

    const int GSMEM = 2 * STAGEB;              // 40960
    const int ASMEM = AQB + 2 * ASTG;          // 55296
    cudaFuncSetAttribute(gemm_f16, cudaFuncAttributeMaxDynamicSharedMemorySize, GSMEM);
    cudaFuncSetAttribute(attn_mma, cudaFuncAttributeMaxDynamicSharedMemorySize, ASMEM);

    // single fused prep launch (residual + 3 weights + W_O transpose)
    prep_all<<<4608, 256>>>(residual, W_Q, W_K, W_V, W_O);

    // QKV projections -> fp16, scattered [b,n,p,h]; Q scale folded into W_Q
    gemm_f16<<<dim3(8, 32, 3), 256, GSMEM>>>(a16, wq, wk, wv,
        nullptr, q16, k16, v16, 1);

    // 1-term fp16 flash attention -> fp16 [b,p,(n,h)]
    attn_mma<<<dim3(SS/128, NH, BB), 256, ASMEM>>>(q16, k16, v16, a216);

    // output projection (fp32 out)
    gemm_f16<<<dim3(8, 32, 1), 256, GSMEM>>>(a216, wo, wo, wo,
        out, nullptr, nullptr, nullptr, 0);
}

// round 10
// speedup vs baseline: 5.7856x; 1.1846x over previous
#include <cuda_runtime.h>
#include <cuda_bf16.h>
#include <cuda_fp16.h>
#include <cstdint>
#include <math.h>

// Problem constants
#define BB 2
#define SS 2048
#define DD 1024
#define NH 16
#define HD 64
#define MM (BB*SS)      // 4096
#define QSCALE 0.18033688011112042f   // 0.125 * log2(e)

// ---------------------------------------------------------------------------
// Scratch (device globals)
// ---------------------------------------------------------------------------
__device__ __align__(16) __half g_A16[MM*DD];       // residual fp16
__device__ __align__(16) __half g_A216[MM*DD];      // attn out fp16
__device__ __align__(16) __half g_WQ16[DD*DD];      // pre-scaled by QSCALE
__device__ __align__(16) __half g_WK16[DD*DD];
__device__ __align__(16) __half g_WV16[DD*DD];
__device__ __align__(16) __half g_WO16[DD*DD];      // transposed W_O
__device__ __align__(16) __half g_Q16[BB*NH*SS*HD];
__device__ __align__(16) __half g_K16[BB*NH*SS*HD];
__device__ __align__(16) __half g_V16[BB*NH*SS*HD];
// dataflow flags: [0,768) qkv tiles (z*256+mt*8+nt); [768,1280) attn ((b*16+qb)*16+n)
__device__ int g_flags[1280];

// ---------------------------------------------------------------------------
// helpers
// ---------------------------------------------------------------------------
__device__ __forceinline__ uint32_t smem_u32(const void* p) {
    uint32_t a;
    asm("{ .reg .u64 t; cvta.to.shared.u64 t, %1; cvt.u32.u64 %0, t; }" : "=r"(a) : "l"(p));
    return a;
}
#define LDSM_X4(r, a) asm volatile("ldmatrix.sync.aligned.m8n8.x4.shared.b16 {%0,%1,%2,%3}, [%4];" \
  : "=r"((r)[0]),"=r"((r)[1]),"=r"((r)[2]),"=r"((r)[3]) : "r"(a))
#define LDSM_X4T(r, a) asm volatile("ldmatrix.sync.aligned.m8n8.x4.trans.shared.b16 {%0,%1,%2,%3}, [%4];" \
  : "=r"((r)[0]),"=r"((r)[1]),"=r"((r)[2]),"=r"((r)[3]) : "r"(a))
#define MMA_F16(d, a, b) asm volatile( \
  "mma.sync.aligned.m16n8k16.row.col.f32.f16.f16.f32 {%0,%1,%2,%3},{%4,%5,%6,%7},{%8,%9},{%0,%1,%2,%3};" \
  : "+f"((d)[0]), "+f"((d)[1]), "+f"((d)[2]), "+f"((d)[3]) \
  : "r"((a)[0]),"r"((a)[1]),"r"((a)[2]),"r"((a)[3]), "r"((b)[0]),"r"((b)[1]))
#define CP_ASYNC16(dst, src) asm volatile("cp.async.cg.shared.global [%0], [%1], 16;" :: "r"(dst), "l"(src))
#define CP_COMMIT() asm volatile("cp.async.commit_group;" ::: "memory")
#define CP_WAIT0()  asm volatile("cp.async.wait_group 0;" ::: "memory")
#define CP_WAIT1()  asm volatile("cp.async.wait_group 1;" ::: "memory")

__device__ __forceinline__ float ex2f(float x) {
    float y; asm("ex2.approx.ftz.f32 %0, %1;" : "=f"(y) : "f"(x)); return y;
}
__device__ __forceinline__ uint32_t pack_h2(float a, float b) {
    uint32_t u;
    asm("{ .reg .f16 lo, hi; cvt.rn.f16.f32 lo, %1; cvt.rn.f16.f32 hi, %2; mov.b32 %0, {lo, hi}; }"
        : "=r"(u) : "f"(a), "f"(b));
    return u;
}
__device__ __forceinline__ void wait_flag(int i) {
    volatile int* f = (volatile int*)&g_flags[i];
    while (*f == 0) { __nanosleep(64); }
}

// ---------------------------------------------------------------------------
// Fused prep + flag reset (one launch, runs before the worker kernel).
// blocks [0, 2048)    : residual -> g_A16
// blocks [2048, 2560) : W_Q * QSCALE -> g_WQ16
// blocks [2560, 3072) : W_K -> g_WK16
// blocks [3072, 3584) : W_V -> g_WV16
// blocks [3584, 4608) : W_O transpose -> g_WO16
// block 0 additionally zeroes g_flags.
// ---------------------------------------------------------------------------
__global__ __launch_bounds__(256) void prep_all(
    const float* __restrict__ residual, const float* __restrict__ W_Q,
    const float* __restrict__ W_K, const float* __restrict__ W_V,
    const float* __restrict__ W_O)
{
    int blk = blockIdx.x;
    if (blk == 0) {
        for (int i = threadIdx.x; i < 1280; i += 256) g_flags[i] = 0;
    }
    if (blk < 3584) {
        const float* src;
        __half* dst;
        float sc = 1.0f;
        int base;
        if (blk < 2048)      { src = residual; dst = g_A16;  base = blk; }
        else if (blk < 2560) { src = W_Q; dst = g_WQ16; base = blk - 2048; sc = QSCALE; }
        else if (blk < 3072) { src = W_K; dst = g_WK16; base = blk - 2560; }
        else                 { src = W_V; dst = g_WV16; base = blk - 3072; }
        int idx = base * 256 + threadIdx.x;
        const float4* s = (const float4*)src + (size_t)idx * 2;
        float4 a0 = s[0], a1 = s[1];
        uint32_t o[4];
        o[0] = pack_h2(a0.x * sc, a0.y * sc);
        o[1] = pack_h2(a0.z * sc, a0.w * sc);
        o[2] = pack_h2(a1.x * sc, a1.y * sc);
        o[3] = pack_h2(a1.z * sc, a1.w * sc);
        ((uint4*)dst)[idx] = *(uint4*)o;
    } else {
        __shared__ float t[32][33];
        int tile = blk - 3584;
        int bx = (tile & 31) * 32;
        int by = (tile >> 5) * 32;
        int tx = threadIdx.x & 31, ty = threadIdx.x >> 5;
        #pragma unroll
        for (int i = 0; i < 4; i++)
            t[ty + 8*i][tx] = W_O[(size_t)(by + ty + 8*i) * DD + bx + tx];
        __syncthreads();
        #pragma unroll
        for (int i = 0; i < 4; i++) {
            float v = t[tx][ty + 8*i];
            g_WO16[(size_t)(bx + ty + 8*i) * DD + by + tx] = __float2half_rn(v);
        }
    }
}

// ---------------------------------------------------------------------------
// GEMM body: C[128x128 tile at m0,n0] = A[128xK] * B[128xK]^T, fp16 in, fp32 acc.
// o16 != nullptr: scatter fp16 to [b,n,p,h]; else fp32 row-major to of.
// ---------------------------------------------------------------------------
#define ROWB 80
#define MATB (128*ROWB)
#define STAGEB (2*MATB)

__device__ __forceinline__ void gemm_body(char* smem,
    const __half* __restrict__ A, const __half* __restrict__ B,
    int m0, int n0, __half* __restrict__ o16, float* __restrict__ of)
{
    const int tid = threadIdx.x, lane = tid & 31, wid = tid >> 5;
    const int wm = wid & 3, wn = wid >> 2;
    const __half* gsrc[2] = { A, B };

    const uint32_t sbase = smem_u32(smem);
    const int lrow = tid >> 2;
    const int lseg = tid & 3;
    const int g = lane >> 3, rl = lane & 7;

    float acc[2][8][4];
    #pragma unroll
    for (int t = 0; t < 2; t++)
        #pragma unroll
        for (int j = 0; j < 8; j++)
            #pragma unroll
            for (int x = 0; x < 4; x++) acc[t][j][x] = 0.f;

    {
        #pragma unroll
        for (int i = 0; i < 4; i++) {
            int mat = i >> 1;
            int r = ((i & 1) << 6) | lrow;
            CP_ASYNC16(sbase + mat * MATB + r * ROWB + lseg * 16,
                       gsrc[mat] + (size_t)r * DD + lseg * 8);
        }
        CP_COMMIT();
    }

    for (int it = 0; it < 32; it++) {
        CP_WAIT0();
        __syncthreads();
        if (it + 1 < 32) {
            int k0 = (it + 1) * 32;
            uint32_t sb = sbase + ((it + 1) & 1) * STAGEB;
            #pragma unroll
            for (int i = 0; i < 4; i++) {
                int mat = i >> 1;
                int r = ((i & 1) << 6) | lrow;
                CP_ASYNC16(sb + mat * MATB + r * ROWB + lseg * 16,
                           gsrc[mat] + (size_t)r * DD + k0 + lseg * 8);
            }
            CP_COMMIT();
        }

        const uint32_t st = sbase + (it & 1) * STAGEB;
        #pragma unroll
        for (int kh = 0; kh < 2; kh++) {
            uint32_t af[2][4], bf[4][4];
            #pragma unroll
            for (int t = 0; t < 2; t++) {
                int row = wm * 32 + t * 16 + (lane & 15);
                LDSM_X4(af[t], st + row * ROWB + (lane >> 4) * 16 + kh * 32);
            }
            #pragma unroll
            for (int jp = 0; jp < 4; jp++) {
                int row = wn * 64 + (2 * jp + (g >> 1)) * 8 + rl;
                LDSM_X4(bf[jp], st + MATB + row * ROWB + (g & 1) * 16 + kh * 32);
            }
            #pragma unroll
            for (int t = 0; t < 2; t++)
                #pragma unroll
                for (int jp = 0; jp < 4; jp++) {
                    MMA_F16(acc[t][2*jp],   af[t], bf[jp]);
                    MMA_F16(acc[t][2*jp+1], af[t], bf[jp]+2);
                }
        }
        __syncthreads();
    }

    const int r0 = lane >> 2, c0 = (lane & 3) * 2;
    #pragma unroll
    for (int t = 0; t < 2; t++) {
        #pragma unroll
        for (int j = 0; j < 8; j++) {
            int o = n0 + wn * 64 + j * 8 + c0;
            #pragma unroll
            for (int h2 = 0; h2 < 2; h2++) {
                int m = m0 + wm * 32 + t * 16 + r0 + h2 * 8;
                float x0 = acc[t][j][2*h2], x1 = acc[t][j][2*h2+1];
                if (o16) {
                    int b = m >> 11, p = m & 2047;
                    int n = o >> 6, hh = o & 63;
                    size_t didx = ((size_t)(b * NH + n) * SS + p) * HD + hh;
                    *(uint32_t*)(o16 + didx) = pack_h2(x0, x1);
                } else {
                    *(float2*)(of + (size_t)m * DD + o) = make_float2(x0, x1);
                }
            }
        }
    }
}

// ---------------------------------------------------------------------------
// Attention body (causal), 1-term fp16, exp2-domain softmax.
// 128 q-rows (block qb), head n, batch b. Writes fp16 [b,p,(n,h)].
// ---------------------------------------------------------------------------
#define AROWB 144
#define AMAT  (64*AROWB)
#define ASTG  (2*AMAT)
#define AQB   (128*AROWB)

__device__ __forceinline__ void attn_body(char* smem,
    const __half* __restrict__ Qg, const __half* __restrict__ Kg,
    const __half* __restrict__ Vg, __half* __restrict__ Og,
    int qb, int n, int b)
{
    const uint32_t sb = smem_u32(smem);
    const int tid = threadIdx.x, lane = tid & 31, wid = tid >> 5;
    const int q0 = qb * 128;
    const size_t base = (size_t)(b * NH + n) * SS * HD;
    const int nt = 2 * qb + 2;
    const uint32_t ST0 = sb + AQB;

    auto load_tile = [&](int t) {
        uint32_t stb = ST0 + (uint32_t)(t & 1) * ASTG;
        int key0 = t * 64;
        const __half* ms[2] = { Kg + base + (size_t)key0 * HD, Vg + base + (size_t)key0 * HD };
        #pragma unroll
        for (int mt = 0; mt < 2; mt++) {
            #pragma unroll
            for (int u = 0; u < 2; u++) {
                int idx = tid + u * 256;
                int row = idx >> 3, seg = idx & 7;
                CP_ASYNC16(stb + mt * AMAT + row * AROWB + seg * 16,
                           ms[mt] + (size_t)row * HD + seg * 8);
            }
        }
    };

    {
        const __half* qs = Qg + base + (size_t)q0 * HD;
        #pragma unroll
        for (int u = 0; u < 4; u++) {
            int idx = tid + u * 256;
            int row = idx >> 3, seg = idx & 7;
            CP_ASYNC16(sb + row * AROWB + seg * 16, qs + (size_t)row * HD + seg * 8);
        }
        load_tile(0);
        CP_COMMIT();
        load_tile(1);
        CP_COMMIT();
    }

    CP_WAIT1();
    __syncthreads();

    uint32_t qf[4][4];
    const int qw = wid * 16;
    #pragma unroll
    for (int kh = 0; kh < 4; kh++) {
        uint32_t a = sb + (qw + (lane & 15)) * AROWB + kh * 32 + (lane >> 4) * 16;
        LDSM_X4(qf[kh], a);
    }

    float m0r = -1e30f, m1r = -1e30f, l0r = 0.f, l1r = 0.f;
    float O[8][4];
    #pragma unroll
    for (int j = 0; j < 8; j++)
        #pragma unroll
        for (int x = 0; x < 4; x++) O[j][x] = 0.f;

    const int row0 = q0 + qw + (lane >> 2);
    const int cl = (lane & 3) * 2;

    for (int it = 0; it < nt; it++) {
        const uint32_t stb = ST0 + (uint32_t)(it & 1) * ASTG;

        float S[8][4];
        #pragma unroll
        for (int j = 0; j < 8; j++)
            #pragma unroll
            for (int x = 0; x < 4; x++) S[j][x] = 0.f;

        #pragma unroll
        for (int kh = 0; kh < 4; kh++) {
            uint32_t kb[4][4];
            const int g = lane >> 3, r = lane & 7;
            #pragma unroll
            for (int jp = 0; jp < 4; jp++) {
                uint32_t a = stb + (uint32_t)(((jp * 2 + (g >> 1)) * 8 + r) * AROWB + (g & 1) * 16 + kh * 32);
                LDSM_X4(kb[jp], a);
            }
            #pragma unroll
            for (int jp = 0; jp < 4; jp++) {
                MMA_F16(S[2*jp],   qf[kh], kb[jp]);
                MMA_F16(S[2*jp+1], qf[kh], kb[jp]+2);
            }
        }

        if (it >= nt - 2) {
            const int kbase = it * 64 + cl;
            #pragma unroll
            for (int j = 0; j < 8; j++) {
                int c = kbase + j * 8;
                if (c     > row0)     S[j][0] = -1e30f;
                if (c + 1 > row0)     S[j][1] = -1e30f;
                if (c     > row0 + 8) S[j][2] = -1e30f;
                if (c + 1 > row0 + 8) S[j][3] = -1e30f;
            }
        }

        float mn0 = m0r, mn1 = m1r;
        #pragma unroll
        for (int j = 0; j < 8; j++) {
            mn0 = fmaxf(mn0, fmaxf(S[j][0], S[j][1]));
            mn1 = fmaxf(mn1, fmaxf(S[j][2], S[j][3]));
        }
        mn0 = fmaxf(mn0, __shfl_xor_sync(0xffffffffu, mn0, 1));
        mn0 = fmaxf(mn0, __shfl_xor_sync(0xffffffffu, mn0, 2));
        mn1 = fmaxf(mn1, __shfl_xor_sync(0xffffffffu, mn1, 1));
        mn1 = fmaxf(mn1, __shfl_xor_sync(0xffffffffu, mn1, 2));

        float c0 = ex2f(m0r - mn0), c1 = ex2f(m1r - mn1);
        l0r *= c0; l1r *= c1;
        #pragma unroll
        for (int j = 0; j < 8; j++) {
            O[j][0] *= c0; O[j][1] *= c0; O[j][2] *= c1; O[j][3] *= c1;
        }
        m0r = mn0; m1r = mn1;

        uint32_t ph[4][4];
        float s0 = 0.f, s1 = 0.f;
        #pragma unroll
        for (int j = 0; j < 8; j++) {
            float p0 = ex2f(S[j][0] - mn0), p1 = ex2f(S[j][1] - mn0);
            float p2 = ex2f(S[j][2] - mn1), p3 = ex2f(S[j][3] - mn1);
            s0 += p0 + p1; s1 += p2 + p3;
            int kk = j >> 1, i0 = (j & 1) * 2;
            ph[kk][i0]   = pack_h2(p0, p1);
            ph[kk][i0+1] = pack_h2(p2, p3);
        }
        s0 += __shfl_xor_sync(0xffffffffu, s0, 1);
        s0 += __shfl_xor_sync(0xffffffffu, s0, 2);
        s1 += __shfl_xor_sync(0xffffffffu, s1, 1);
        s1 += __shfl_xor_sync(0xffffffffu, s1, 2);
        l0r += s0; l1r += s1;

        {
            const int g = lane >> 3, r = lane & 7;
            #pragma unroll
            for (int kk = 0; kk < 4; kk++) {
                #pragma unroll
                for (int jn = 0; jn < 4; jn++) {
                    uint32_t vb[4];
                    uint32_t a = stb + AMAT
                        + (uint32_t)((kk * 16 + ((g & 1) << 3) + r) * AROWB + (2 * jn + (g >> 1)) * 16);
                    LDSM_X4T(vb, a);
                    MMA_F16(O[2*jn],   ph[kk], vb);
                    MMA_F16(O[2*jn+1], ph[kk], vb+2);
                }
            }
        }

        __syncthreads();
        int nx = it + 2;
        if (nx < nt) { load_tile(nx); CP_COMMIT(); }
        if (it + 1 < nt) {
            if (nx < nt) CP_WAIT1(); else CP_WAIT0();
            __syncthreads();
        }
    }

    float inv0 = 1.f / l0r, inv1 = 1.f / l1r;
    size_t orow0 = ((size_t)(b * SS + row0)) * DD + n * HD;
    size_t orow1 = orow0 + (size_t)8 * DD;
    #pragma unroll
    for (int nb = 0; nb < 8; nb++) {
        int d = nb * 8 + cl;
        *(uint32_t*)(Og + orow0 + d) = pack_h2(O[nb][0] * inv0, O[nb][1] * inv0);
        *(uint32_t*)(Og + orow1 + d) = pack_h2(O[nb][2] * inv1, O[nb][3] * inv1);
    }
}

// ---------------------------------------------------------------------------
// Fused dataflow worker: ids [0,768) QKV gemm tiles, [768,1280) attention,
// [1280,1536) O-projection tiles. Dependencies via g_flags (release/acquire).
// ---------------------------------------------------------------------------
#define WSMEM (AQB + 2*ASTG)   // 55296 >= gemm's 40960

__global__ __launch_bounds__(256, 2) void worker(
    const __half* __restrict__ a16,
    const __half* __restrict__ wq, const __half* __restrict__ wk,
    const __half* __restrict__ wv, const __half* __restrict__ wo,
    __half* __restrict__ q16, __half* __restrict__ k16, __half* __restrict__ v16,
    __half* __restrict__ a216, float* __restrict__ out)
{
    extern __shared__ char smem[];
    const int id = blockIdx.x;
    const int tid = threadIdx.x;

    if (id < 768) {
        // ---- QKV projection tile
        int mt = id / 24;
        int rem = id % 24;
        int z = rem >> 3, ntl = rem & 7;
        const __half* B = (z == 0) ? wq : (z == 1) ? wk : wv;
        __half* o16 = (z == 0) ? q16 : (z == 1) ? k16 : v16;
        gemm_body(smem, a16 + (size_t)mt * 128 * DD, B + (size_t)ntl * 128 * DD,
                  mt * 128, ntl * 128, o16, nullptr);
        __syncthreads();
        __threadfence();
        if (tid == 0) atomicExch(&g_flags[z * 256 + mt * 8 + ntl], 1);
    } else if (id < 1280) {
        // ---- attention block: qb descending (long CTAs grab slots first)
        int a = id - 768;
        int qb = 15 - (a >> 5);
        int rem = a & 31;
        int b = rem >> 4, n = rem & 15;
        if (tid == 0) {
            int ntc = n >> 1;
            wait_flag(0 * 256 + (b * 16 + qb) * 8 + ntc);          // Q tile
            for (int j = 0; j <= qb; j++) {
                wait_flag(1 * 256 + (b * 16 + j) * 8 + ntc);       // K tiles
                wait_flag(2 * 256 + (b * 16 + j) * 8 + ntc);       // V tiles
            }
            __threadfence();
        }
        __syncthreads();
        attn_body(smem, q16, k16, v16, a216, qb, n, b);
        __syncthreads();
        __threadfence();
        if (tid == 0) atomicExch(&g_flags[768 + (b * 16 + qb) * 16 + n], 1);
    } else {
        // ---- O-projection tile: ascending qb (dep readiness order)
        int o = id - 1280;
        int qb2 = o >> 3;                 // qb*2 + b
        int ntl = o & 7;
        int qb = qb2 >> 1, b = qb2 & 1;
        int mt = b * 16 + qb;
        if (tid == 0) {
            for (int n = 0; n < 16; n++)
                wait_flag(768 + (b * 16 + qb) * 16 + n);
            __threadfence();
        }
        __syncthreads();
        gemm_body(smem, a216 + (size_t)mt * 128 * DD, wo + (size_t)ntl * 128 * DD,
                  mt * 128, ntl * 128, nullptr, out);
    }
}

// ---------------------------------------------------------------------------
extern "C" void kernel_launch(void* const* d_in, const int* in_sizes, int n_in,
                              void* d_out, int out_size)
{
    const float* residual = (const float*)d_in[0];
    const float* W_Q = (const float*)d_in[1];
    const float* W_K = (const float*)d_in[2];
    const float* W_V = (const float*)d_in[3];
    const float* W_O = (const float*)d_in[4];
    float* out = (float*)d_out;

    __half *a16, *a216, *wq, *wk, *wv, *wo, *q16, *k16, *v16;
    cudaGetSymbolAddress((void**)&a16,  g_A16);
    cudaGetSymbolAddress((void**)&a216, g_A216);
    cudaGetSymbolAddress((void**)&wq,   g_WQ16);
    cudaGetSymbolAddress((void**)&wk,   g_WK16);
    cudaGetSymbolAddress((void**)&wv,   g_WV16);
    cudaGetSymbolAddress((void**)&wo,   g_WO16);
    cudaGetSymbolAddress((void**)&q16,  g_Q16);
    cudaGetSymbolAddress((void**)&k16,  g_K16);
    cudaGetSymbolAddress((void**)&v16,  g_V16);

    cudaFuncSetAttribute(worker, cudaFuncAttributeMaxDynamicSharedMemorySize, WSMEM);

    // prep + flag reset (ordering with worker guaranteed by stream order)
    prep_all<<<4608, 256>>>(residual, W_Q, W_K, W_V, W_O);

    // fused QKV -> attention -> O-projection dataflow kernel
    worker<<<1536, 256, WSMEM>>>(a16, wq, wk, wv, wo, q16, k16, v16, a216, out);
}

// round 11
// speedup vs baseline: 5.8146x; 1.0050x over previous
#include <cuda_runtime.h>
#include <cuda_bf16.h>
#include <cuda_fp16.h>
#include <cstdint>
#include <math.h>

// Problem constants
#define BB 2
#define SS 2048
#define DD 1024
#define NH 16
#define HD 64
#define MM (BB*SS)      // 4096
#define QSCALE 0.18033688011112042f   // 0.125 * log2(e)

// ---------------------------------------------------------------------------
// Scratch (device globals)
// ---------------------------------------------------------------------------
__device__ __align__(16) __half g_A16[MM*DD];       // residual fp16
__device__ __align__(16) __half g_A216[MM*DD];      // attn out fp16
__device__ __align__(16) __half g_WQ16[DD*DD];      // pre-scaled by QSCALE
__device__ __align__(16) __half g_WK16[DD*DD];
__device__ __align__(16) __half g_WV16[DD*DD];
__device__ __align__(16) __half g_WO16[DD*DD];      // transposed W_O
__device__ __align__(16) __half g_Q16[BB*NH*SS*HD];
__device__ __align__(16) __half g_K16[BB*NH*SS*HD];
__device__ __align__(16) __half g_V16[BB*NH*SS*HD];
// dataflow flags: [0,768) qkv tiles (z*256+mt*8+ntc); [768,1280) attn ((b*16+qb)*16+n)
__device__ int g_flags[1280];

// ---------------------------------------------------------------------------
// helpers
// ---------------------------------------------------------------------------
__device__ __forceinline__ uint32_t smem_u32(const void* p) {
    uint32_t a;
    asm("{ .reg .u64 t; cvta.to.shared.u64 t, %1; cvt.u32.u64 %0, t; }" : "=r"(a) : "l"(p));
    return a;
}
#define LDSM_X4(r, a) asm volatile("ldmatrix.sync.aligned.m8n8.x4.shared.b16 {%0,%1,%2,%3}, [%4];" \
  : "=r"((r)[0]),"=r"((r)[1]),"=r"((r)[2]),"=r"((r)[3]) : "r"(a))
#define LDSM_X4T(r, a) asm volatile("ldmatrix.sync.aligned.m8n8.x4.trans.shared.b16 {%0,%1,%2,%3}, [%4];" \
  : "=r"((r)[0]),"=r"((r)[1]),"=r"((r)[2]),"=r"((r)[3]) : "r"(a))
#define MMA_F16(d, a, b) asm volatile( \
  "mma.sync.aligned.m16n8k16.row.col.f32.f16.f16.f32 {%0,%1,%2,%3},{%4,%5,%6,%7},{%8,%9},{%0,%1,%2,%3};" \
  : "+f"((d)[0]), "+f"((d)[1]), "+f"((d)[2]), "+f"((d)[3]) \
  : "r"((a)[0]),"r"((a)[1]),"r"((a)[2]),"r"((a)[3]), "r"((b)[0]),"r"((b)[1]))
#define CP_ASYNC16(dst, src) asm volatile("cp.async.cg.shared.global [%0], [%1], 16;" :: "r"(dst), "l"(src))
#define CP_COMMIT() asm volatile("cp.async.commit_group;" ::: "memory")
#define CP_WAIT0()  asm volatile("cp.async.wait_group 0;" ::: "memory")
#define CP_WAIT1()  asm volatile("cp.async.wait_group 1;" ::: "memory")

__device__ __forceinline__ float ex2f(float x) {
    float y; asm("ex2.approx.ftz.f32 %0, %1;" : "=f"(y) : "f"(x)); return y;
}
__device__ __forceinline__ uint32_t pack_h2(float a, float b) {
    uint32_t u;
    asm("{ .reg .f16 lo, hi; cvt.rn.f16.f32 lo, %1; cvt.rn.f16.f32 hi, %2; mov.b32 %0, {lo, hi}; }"
        : "=r"(u) : "f"(a), "f"(b));
    return u;
}
__device__ __forceinline__ void wait_flag(int i) {
    volatile int* f = (volatile int*)&g_flags[i];
    while (*f == 0) { __nanosleep(64); }
}

// ---------------------------------------------------------------------------
// Fused prep + flag reset (one launch, runs before the worker kernel).
// ---------------------------------------------------------------------------
__global__ __launch_bounds__(256) void prep_all(
    const float* __restrict__ residual, const float* __restrict__ W_Q,
    const float* __restrict__ W_K, const float* __restrict__ W_V,
    const float* __restrict__ W_O)
{
    int blk = blockIdx.x;
    if (blk == 0) {
        for (int i = threadIdx.x; i < 1280; i += 256) g_flags[i] = 0;
    }
    if (blk < 3584) {
        const float* src;
        __half* dst;
        float sc = 1.0f;
        int base;
        if (blk < 2048)      { src = residual; dst = g_A16;  base = blk; }
        else if (blk < 2560) { src = W_Q; dst = g_WQ16; base = blk - 2048; sc = QSCALE; }
        else if (blk < 3072) { src = W_K; dst = g_WK16; base = blk - 2560; }
        else                 { src = W_V; dst = g_WV16; base = blk - 3072; }
        int idx = base * 256 + threadIdx.x;
        const float4* s = (const float4*)src + (size_t)idx * 2;
        float4 a0 = s[0], a1 = s[1];
        uint32_t o[4];
        o[0] = pack_h2(a0.x * sc, a0.y * sc);
        o[1] = pack_h2(a0.z * sc, a0.w * sc);
        o[2] = pack_h2(a1.x * sc, a1.y * sc);
        o[3] = pack_h2(a1.z * sc, a1.w * sc);
        ((uint4*)dst)[idx] = *(uint4*)o;
    } else {
        __shared__ float t[32][33];
        int tile = blk - 3584;
        int bx = (tile & 31) * 32;
        int by = (tile >> 5) * 32;
        int tx = threadIdx.x & 31, ty = threadIdx.x >> 5;
        #pragma unroll
        for (int i = 0; i < 4; i++)
            t[ty + 8*i][tx] = W_O[(size_t)(by + ty + 8*i) * DD + bx + tx];
        __syncthreads();
        #pragma unroll
        for (int i = 0; i < 4; i++) {
            float v = t[tx][ty + 8*i];
            g_WO16[(size_t)(bx + ty + 8*i) * DD + by + tx] = __float2half_rn(v);
        }
    }
}

// ---------------------------------------------------------------------------
// GEMM body: C[128x128 tile at m0,n0] = A[128xK] * B[128xK]^T, fp16 in, fp32 acc.
// o16 != nullptr: scatter fp16 to [b,n,p,h]; else fp32 row-major to of.
// ---------------------------------------------------------------------------
#define ROWB 80
#define MATB (128*ROWB)
#define STAGEB (2*MATB)

__device__ __forceinline__ void gemm_body(char* smem,
    const __half* __restrict__ A, const __half* __restrict__ B,
    int m0, int n0, __half* __restrict__ o16, float* __restrict__ of)
{
    const int tid = threadIdx.x, lane = tid & 31, wid = tid >> 5;
    const int wm = wid & 3, wn = wid >> 2;
    const __half* gsrc[2] = { A, B };

    const uint32_t sbase = smem_u32(smem);
    const int lrow = tid >> 2;
    const int lseg = tid & 3;
    const int g = lane >> 3, rl = lane & 7;

    float acc[2][8][4];
    #pragma unroll
    for (int t = 0; t < 2; t++)
        #pragma unroll
        for (int j = 0; j < 8; j++)
            #pragma unroll
            for (int x = 0; x < 4; x++) acc[t][j][x] = 0.f;

    {
        #pragma unroll
        for (int i = 0; i < 4; i++) {
            int mat = i >> 1;
            int r = ((i & 1) << 6) | lrow;
            CP_ASYNC16(sbase + mat * MATB + r * ROWB + lseg * 16,
                       gsrc[mat] + (size_t)r * DD + lseg * 8);
        }
        CP_COMMIT();
    }

    for (int it = 0; it < 32; it++) {
        CP_WAIT0();
        __syncthreads();
        if (it + 1 < 32) {
            int k0 = (it + 1) * 32;
            uint32_t sb = sbase + ((it + 1) & 1) * STAGEB;
            #pragma unroll
            for (int i = 0; i < 4; i++) {
                int mat = i >> 1;
                int r = ((i & 1) << 6) | lrow;
                CP_ASYNC16(sb + mat * MATB + r * ROWB + lseg * 16,
                           gsrc[mat] + (size_t)r * DD + k0 + lseg * 8);
            }
            CP_COMMIT();
        }

        const uint32_t st = sbase + (it & 1) * STAGEB;
        #pragma unroll
        for (int kh = 0; kh < 2; kh++) {
            uint32_t af[2][4], bf[4][4];
            #pragma unroll
            for (int t = 0; t < 2; t++) {
                int row = wm * 32 + t * 16 + (lane & 15);
                LDSM_X4(af[t], st + row * ROWB + (lane >> 4) * 16 + kh * 32);
            }
            #pragma unroll
            for (int jp = 0; jp < 4; jp++) {
                int row = wn * 64 + (2 * jp + (g >> 1)) * 8 + rl;
                LDSM_X4(bf[jp], st + MATB + row * ROWB + (g & 1) * 16 + kh * 32);
            }
            #pragma unroll
            for (int t = 0; t < 2; t++)
                #pragma unroll
                for (int jp = 0; jp < 4; jp++) {
                    MMA_F16(acc[t][2*jp],   af[t], bf[jp]);
                    MMA_F16(acc[t][2*jp+1], af[t], bf[jp]+2);
                }
        }
        __syncthreads();
    }

    const int r0 = lane >> 2, c0 = (lane & 3) * 2;
    #pragma unroll
    for (int t = 0; t < 2; t++) {
        #pragma unroll
        for (int j = 0; j < 8; j++) {
            int o = n0 + wn * 64 + j * 8 + c0;
            #pragma unroll
            for (int h2 = 0; h2 < 2; h2++) {
                int m = m0 + wm * 32 + t * 16 + r0 + h2 * 8;
                float x0 = acc[t][j][2*h2], x1 = acc[t][j][2*h2+1];
                if (o16) {
                    int b = m >> 11, p = m & 2047;
                    int n = o >> 6, hh = o & 63;
                    size_t didx = ((size_t)(b * NH + n) * SS + p) * HD + hh;
                    *(uint32_t*)(o16 + didx) = pack_h2(x0, x1);
                } else {
                    *(float2*)(of + (size_t)m * DD + o) = make_float2(x0, x1);
                }
            }
        }
    }
}

// ---------------------------------------------------------------------------
// Attention body (causal), 1-term fp16, exp2 softmax, STREAMING K/V flag waits.
// ---------------------------------------------------------------------------
#define AROWB 144
#define AMAT  (64*AROWB)
#define ASTG  (2*AMAT)
#define AQB   (128*AROWB)

__device__ __forceinline__ void attn_body(char* smem,
    const __half* __restrict__ Qg, const __half* __restrict__ Kg,
    const __half* __restrict__ Vg, __half* __restrict__ Og,
    int qb, int n, int b)
{
    const uint32_t sb = smem_u32(smem);
    const int tid = threadIdx.x, lane = tid & 31, wid = tid >> 5;
    const int q0 = qb * 128;
    const size_t base = (size_t)(b * NH + n) * SS * HD;
    const int nt = 2 * qb + 2;
    const uint32_t ST0 = sb + AQB;
    const int ntc = n >> 1;

    auto wait_kv = [&](int j) {
        wait_flag(1 * 256 + (b * 16 + j) * 8 + ntc);   // K tile
        wait_flag(2 * 256 + (b * 16 + j) * 8 + ntc);   // V tile
    };

    auto load_tile = [&](int t) {
        uint32_t stb = ST0 + (uint32_t)(t & 1) * ASTG;
        int key0 = t * 64;
        const __half* ms[2] = { Kg + base + (size_t)key0 * HD, Vg + base + (size_t)key0 * HD };
        #pragma unroll
        for (int mt = 0; mt < 2; mt++) {
            #pragma unroll
            for (int u = 0; u < 2; u++) {
                int idx = tid + u * 256;
                int row = idx >> 3, seg = idx & 7;
                CP_ASYNC16(stb + mt * AMAT + row * AROWB + seg * 16,
                           ms[mt] + (size_t)row * HD + seg * 8);
            }
        }
    };

    // upfront deps: own Q tile + K/V rows j=0 (covers k-tiles 0 and 1)
    if (tid == 0) {
        wait_flag(0 * 256 + (b * 16 + qb) * 8 + ntc);
        wait_kv(0);
    }
    __syncthreads();

    {
        const __half* qs = Qg + base + (size_t)q0 * HD;
        #pragma unroll
        for (int u = 0; u < 4; u++) {
            int idx = tid + u * 256;
            int row = idx >> 3, seg = idx & 7;
            CP_ASYNC16(sb + row * AROWB + seg * 16, qs + (size_t)row * HD + seg * 8);
        }
        load_tile(0);
        CP_COMMIT();
        load_tile(1);
        CP_COMMIT();
    }

    CP_WAIT1();
    __syncthreads();

    uint32_t qf[4][4];
    const int qw = wid * 16;
    #pragma unroll
    for (int kh = 0; kh < 4; kh++) {
        uint32_t a = sb + (qw + (lane & 15)) * AROWB + kh * 32 + (lane >> 4) * 16;
        LDSM_X4(qf[kh], a);
    }

    float m0r = -1e30f, m1r = -1e30f, l0r = 0.f, l1r = 0.f;
    float O[8][4];
    #pragma unroll
    for (int j = 0; j < 8; j++)
        #pragma unroll
        for (int x = 0; x < 4; x++) O[j][x] = 0.f;

    const int row0 = q0 + qw + (lane >> 2);
    const int cl = (lane & 3) * 2;

    for (int it = 0; it < nt; it++) {
        const uint32_t stb = ST0 + (uint32_t)(it & 1) * ASTG;

        float S[8][4];
        #pragma unroll
        for (int j = 0; j < 8; j++)
            #pragma unroll
            for (int x = 0; x < 4; x++) S[j][x] = 0.f;

        #pragma unroll
        for (int kh = 0; kh < 4; kh++) {
            uint32_t kb[4][4];
            const int g = lane >> 3, r = lane & 7;
            #pragma unroll
            for (int jp = 0; jp < 4; jp++) {
                uint32_t a = stb + (uint32_t)(((jp * 2 + (g >> 1)) * 8 + r) * AROWB + (g & 1) * 16 + kh * 32);
                LDSM_X4(kb[jp], a);
            }
            #pragma unroll
            for (int jp = 0; jp < 4; jp++) {
                MMA_F16(S[2*jp],   qf[kh], kb[jp]);
                MMA_F16(S[2*jp+1], qf[kh], kb[jp]+2);
            }
        }

        if (it >= nt - 2) {
            const int kbase = it * 64 + cl;
            #pragma unroll
            for (int j = 0; j < 8; j++) {
                int c = kbase + j * 8;
                if (c     > row0)     S[j][0] = -1e30f;
                if (c + 1 > row0)     S[j][1] = -1e30f;
                if (c     > row0 + 8) S[j][2] = -1e30f;
                if (c + 1 > row0 + 8) S[j][3] = -1e30f;
            }
        }

        float mn0 = m0r, mn1 = m1r;
        #pragma unroll
        for (int j = 0; j < 8; j++) {
            mn0 = fmaxf(mn0, fmaxf(S[j][0], S[j][1]));
            mn1 = fmaxf(mn1, fmaxf(S[j][2], S[j][3]));
        }
        mn0 = fmaxf(mn0, __shfl_xor_sync(0xffffffffu, mn0, 1));
        mn0 = fmaxf(mn0, __shfl_xor_sync(0xffffffffu, mn0, 2));
        mn1 = fmaxf(mn1, __shfl_xor_sync(0xffffffffu, mn1, 1));
        mn1 = fmaxf(mn1, __shfl_xor_sync(0xffffffffu, mn1, 2));

        float c0 = ex2f(m0r - mn0), c1 = ex2f(m1r - mn1);
        l0r *= c0; l1r *= c1;
        #pragma unroll
        for (int j = 0; j < 8; j++) {
            O[j][0] *= c0; O[j][1] *= c0; O[j][2] *= c1; O[j][3] *= c1;
        }
        m0r = mn0; m1r = mn1;

        uint32_t ph[4][4];
        float s0 = 0.f, s1 = 0.f;
        #pragma unroll
        for (int j = 0; j < 8; j++) {
            float p0 = ex2f(S[j][0] - mn0), p1 = ex2f(S[j][1] - mn0);
            float p2 = ex2f(S[j][2] - mn1), p3 = ex2f(S[j][3] - mn1);
            s0 += p0 + p1; s1 += p2 + p3;
            int kk = j >> 1, i0 = (j & 1) * 2;
            ph[kk][i0]   = pack_h2(p0, p1);
            ph[kk][i0+1] = pack_h2(p2, p3);
        }
        s0 += __shfl_xor_sync(0xffffffffu, s0, 1);
        s0 += __shfl_xor_sync(0xffffffffu, s0, 2);
        s1 += __shfl_xor_sync(0xffffffffu, s1, 1);
        s1 += __shfl_xor_sync(0xffffffffu, s1, 2);
        l0r += s0; l1r += s1;

        {
            const int g = lane >> 3, r = lane & 7;
            #pragma unroll
            for (int kk = 0; kk < 4; kk++) {
                #pragma unroll
                for (int jn = 0; jn < 4; jn++) {
                    uint32_t vb[4];
                    uint32_t a = stb + AMAT
                        + (uint32_t)((kk * 16 + ((g & 1) << 3) + r) * AROWB + (2 * jn + (g >> 1)) * 16);
                    LDSM_X4T(vb, a);
                    MMA_F16(O[2*jn],   ph[kk], vb);
                    MMA_F16(O[2*jn+1], ph[kk], vb+2);
                }
            }
        }

        __syncthreads();
        int nx = it + 2;
        if (nx < nt) {
            if (tid == 0) wait_kv(nx >> 1);   // streaming dependency
            __syncthreads();
            load_tile(nx);
            CP_COMMIT();
        }
        if (it + 1 < nt) {
            if (nx < nt) CP_WAIT1(); else CP_WAIT0();
            __syncthreads();
        }
    }

    float inv0 = 1.f / l0r, inv1 = 1.f / l1r;
    size_t orow0 = ((size_t)(b * SS + row0)) * DD + n * HD;
    size_t orow1 = orow0 + (size_t)8 * DD;
    #pragma unroll
    for (int nb = 0; nb < 8; nb++) {
        int d = nb * 8 + cl;
        *(uint32_t*)(Og + orow0 + d) = pack_h2(O[nb][0] * inv0, O[nb][1] * inv0);
        *(uint32_t*)(Og + orow1 + d) = pack_h2(O[nb][2] * inv1, O[nb][3] * inv1);
    }
}

// ---------------------------------------------------------------------------
// Fused dataflow worker.
// ids [0,256)   : Q projection tiles, qb DESCENDING (critical first)
// ids [256,768) : K/V projection tiles, key rows j ASCENDING (stream order)
// ids [768,1280): attention blocks, qb descending
// ids [1280,1536): O-projection tiles, qb ascending
// ---------------------------------------------------------------------------
#define WSMEM (AQB + 2*ASTG)   // 55296 >= gemm's 40960

__global__ __launch_bounds__(256, 2) void worker(
    const __half* __restrict__ a16,
    const __half* __restrict__ wq, const __half* __restrict__ wk,
    const __half* __restrict__ wv, const __half* __restrict__ wo,
    __half* __restrict__ q16, __half* __restrict__ k16, __half* __restrict__ v16,
    __half* __restrict__ a216, float* __restrict__ out)
{
    extern __shared__ char smem[];
    const int id = blockIdx.x;
    const int tid = threadIdx.x;

    if (id < 768) {
        // ---- projection tile (criticality-ordered)
        int z, mt, ntl;
        if (id < 256) {
            // Q tiles: qb descending, batches interleaved
            int r = id >> 3;                // 0..31
            int qb = 15 - (r >> 1);
            int b = r & 1;
            mt = b * 16 + qb;
            z = 0;
            ntl = id & 7;
        } else {
            // K/V tiles: j ascending; per j: K(b0,b1) then V(b0,b1)
            int u = id - 256;               // 0..511
            int j = u >> 5;                 // 0..15
            int rem = u & 31;
            z = 1 + (rem >> 4);             // 1=K, 2=V
            int sub = rem & 15;
            int b = sub >> 3;
            ntl = sub & 7;
            mt = b * 16 + j;
        }
        const __half* B = (z == 0) ? wq : (z == 1) ? wk : wv;
        __half* o16 = (z == 0) ? q16 : (z == 1) ? k16 : v16;
        gemm_body(smem, a16 + (size_t)mt * 128 * DD, B + (size_t)ntl * 128 * DD,
                  mt * 128, ntl * 128, o16, nullptr);
        __syncthreads();
        __threadfence();
        if (tid == 0) atomicExch(&g_flags[z * 256 + mt * 8 + ntl], 1);
    } else if (id < 1280) {
        // ---- attention block: qb descending (long CTAs grab slots first)
        int a = id - 768;
        int qb = 15 - (a >> 5);
        int rem = a & 31;
        int b = rem >> 4, n = rem & 15;
        attn_body(smem, q16, k16, v16, a216, qb, n, b);
        __syncthreads();
        __threadfence();
        if (tid == 0) atomicExch(&g_flags[768 + (b * 16 + qb) * 16 + n], 1);
    } else {
        // ---- O-projection tile: ascending qb (dep readiness order)
        int o = id - 1280;
        int qb2 = o >> 3;                 // qb*2 + b
        int ntl = o & 7;
        int qb = qb2 >> 1, b = qb2 & 1;
        int mt = b * 16 + qb;
        if (tid == 0) {
            for (int n = 0; n < 16; n++)
                wait_flag(768 + (b * 16 + qb) * 16 + n);
            __threadfence();
        }
        __syncthreads();
        gemm_body(smem, a216 + (size_t)mt * 128 * DD, wo + (size_t)ntl * 128 * DD,
                  mt * 128, ntl * 128, nullptr, out);
    }
}

// ---------------------------------------------------------------------------
extern "C" void kernel_launch(void* const* d_in, const int* in_sizes, int n_in,
                              void* d_out, int out_size)
{
    const float* residual = (const float*)d_in[0];
    const float* W_Q = (const float*)d_in[1];
    const float* W_K = (const float*)d_in[2];
    const float* W_V = (const float*)d_in[3];
    const float* W_O = (const float*)d_in[4];
    float* out = (float*)d_out;

    __half *a16, *a216, *wq, *wk, *wv, *wo, *q16, *k16, *v16;
    cudaGetSymbolAddress((void**)&a16,  g_A16);
    cudaGetSymbolAddress((void**)&a216, g_A216);
    cudaGetSymbolAddress((void**)&wq,   g_WQ16);
    cudaGetSymbolAddress((void**)&wk,   g_WK16);
    cudaGetSymbolAddress((void**)&wv,   g_WV16);
    cudaGetSymbolAddress((void**)&wo,   g_WO16);
    cudaGetSymbolAddress((void**)&q16,  g_Q16);
    cudaGetSymbolAddress((void**)&k16,  g_K16);
    cudaGetSymbolAddress((void**)&v16,  g_V16);

    cudaFuncSetAttribute(worker, cudaFuncAttributeMaxDynamicSharedMemorySize, WSMEM);

    // prep + flag reset (ordering with worker guaranteed by stream order)
    prep_all<<<4608, 256>>>(residual, W_Q, W_K, W_V, W_O);

    // fused QKV -> attention -> O-projection dataflow kernel
    worker<<<1536, 256, WSMEM>>>(a16, wq, wk, wv, wo, q16, k16, v16, a216, out);
}